// round 1
// baseline (speedup 1.0000x reference)
#include <cuda_runtime.h>
#include <cuda_bf16.h>
#include <cstdint>
#include <cfloat>

// ---------------------------------------------------------------------------
// Problem dims (fixed)
// ---------------------------------------------------------------------------
#define C_DIM   3072
#define HIDDEN  3072
#define KV_DIM  6144
#define N_HEADS 48
#define D_HEAD  64
#define BT      4
#define AA      128
#define HW      1024
#define ROWS_X  (BT * AA)    // 512
#define ROWS_L  (BT * HW)    // 4096

// ---------------------------------------------------------------------------
// Scratch (device globals: allocation-free rule)
// ---------------------------------------------------------------------------
__device__ float g_xn[ROWS_X * C_DIM];      // 6.3 MB
__device__ float g_ln[ROWS_L * C_DIM];      // 50 MB
__device__ float g_q [ROWS_L * HIDDEN];     // 50 MB
__device__ float g_kv[ROWS_X * KV_DIM];     // 12.6 MB
__device__ float g_ao[ROWS_L * HIDDEN];     // 50 MB

// ---------------------------------------------------------------------------
// Helpers
// ---------------------------------------------------------------------------
__device__ __forceinline__ float tf32_rna(float x) {
    uint32_t u;
    asm("cvt.rna.tf32.f32 %0, %1;" : "=r"(u) : "f"(x));
    return __uint_as_float(u);
}

__device__ __forceinline__ void mma_tf32(float* c, const uint32_t* a, const uint32_t* b) {
    asm volatile(
        "mma.sync.aligned.m16n8k8.row.col.f32.tf32.tf32.f32 "
        "{%0,%1,%2,%3}, {%4,%5,%6,%7}, {%8,%9}, {%0,%1,%2,%3};\n"
        : "+f"(c[0]), "+f"(c[1]), "+f"(c[2]), "+f"(c[3])
        : "r"(a[0]), "r"(a[1]), "r"(a[2]), "r"(a[3]), "r"(b[0]), "r"(b[1]));
}

// ---------------------------------------------------------------------------
// LayerNorm: one block per row of 3072
// ---------------------------------------------------------------------------
__global__ __launch_bounds__(256)
void ln_kernel(const float* __restrict__ x, const float* __restrict__ gamma,
               const float* __restrict__ beta, float* __restrict__ y)
{
    const int row = blockIdx.x;
    const int tid = threadIdx.x;
    const float* xr = x + (size_t)row * C_DIM;
    float*       yr = y + (size_t)row * C_DIM;

    float4 v[3];
    float s = 0.f, s2 = 0.f;
#pragma unroll
    for (int j = 0; j < 3; j++) {
        v[j] = *(const float4*)(xr + (size_t)(tid + 256 * j) * 4);
        s  += v[j].x + v[j].y + v[j].z + v[j].w;
        s2 += v[j].x*v[j].x + v[j].y*v[j].y + v[j].z*v[j].z + v[j].w*v[j].w;
    }
#pragma unroll
    for (int o = 16; o > 0; o >>= 1) {
        s  += __shfl_xor_sync(0xffffffffu, s, o);
        s2 += __shfl_xor_sync(0xffffffffu, s2, o);
    }
    __shared__ float red[2][8];
    const int w = tid >> 5, lane = tid & 31;
    if (lane == 0) { red[0][w] = s; red[1][w] = s2; }
    __syncthreads();
    float ts = 0.f, ts2 = 0.f;
#pragma unroll
    for (int i = 0; i < 8; i++) { ts += red[0][i]; ts2 += red[1][i]; }
    const float mean = ts * (1.0f / C_DIM);
    const float var  = ts2 * (1.0f / C_DIM) - mean * mean;
    const float rstd = rsqrtf(var + 1e-5f);

#pragma unroll
    for (int j = 0; j < 3; j++) {
        const int c4 = (tid + 256 * j) * 4;
        float4 g = *(const float4*)(gamma + c4);
        float4 b = *(const float4*)(beta  + c4);
        float4 o;
        o.x = (v[j].x - mean) * rstd * g.x + b.x;
        o.y = (v[j].y - mean) * rstd * g.y + b.y;
        o.z = (v[j].z - mean) * rstd * g.z + b.z;
        o.w = (v[j].w - mean) * rstd * g.w + b.w;
        *(float4*)(yr + c4) = o;
    }
}

// ---------------------------------------------------------------------------
// TF32 GEMM: C[M,N] = A[M,K] * B[K,N], all row-major fp32.
// 128x128x16 block tile, 256 threads (8 warps as 2m x 4n, warp tile 64x32),
// double-buffered smem, cvt.rna.tf32 applied during staging.
// Requires M%128==0, N%128==0, K%16==0 (true for all three GEMMs here).
// ---------------------------------------------------------------------------
__global__ __launch_bounds__(256)
void gemm_tf32(const float* __restrict__ A, const float* __restrict__ B,
               float* __restrict__ C, int M, int N, int K)
{
    __shared__ float As[2][128 * 20];   // row stride 20 floats (conflict-free frags)
    __shared__ float Bs[2][16 * 136];   // row stride 136 floats

    const int tid  = threadIdx.x;
    const int lane = tid & 31;
    const int w    = tid >> 5;
    const int wm   = w >> 2;         // 0..1
    const int wn   = w & 3;          // 0..3
    const int g    = lane >> 2;      // 0..7
    const int tg   = lane & 3;       // 0..3
    const int m0   = blockIdx.y * 128;
    const int n0   = blockIdx.x * 128;

    const int ar = tid >> 2, ac = (tid & 3) * 4;     // A staging: rows ar, ar+64
    const int br = tid >> 5, bc = (tid & 31) * 4;    // B staging: rows br, br+8

    const float* Abase = A + (size_t)m0 * K;
    const float* Bbase = B + n0;

    float acc[4][4][4];
#pragma unroll
    for (int mi = 0; mi < 4; mi++)
#pragma unroll
        for (int ni = 0; ni < 4; ni++)
#pragma unroll
            for (int r = 0; r < 4; r++) acc[mi][ni][r] = 0.f;

    const int nk = K >> 4;
    float4 ra0, ra1, rb0, rb1;

    // prologue: load tile 0
    ra0 = *(const float4*)(Abase + (size_t)ar * K + ac);
    ra1 = *(const float4*)(Abase + (size_t)(ar + 64) * K + ac);
    rb0 = *(const float4*)(Bbase + (size_t)br * N + bc);
    rb1 = *(const float4*)(Bbase + (size_t)(br + 8) * N + bc);
    {
        float4 t;
        t.x = tf32_rna(ra0.x); t.y = tf32_rna(ra0.y); t.z = tf32_rna(ra0.z); t.w = tf32_rna(ra0.w);
        *(float4*)&As[0][ar * 20 + ac] = t;
        t.x = tf32_rna(ra1.x); t.y = tf32_rna(ra1.y); t.z = tf32_rna(ra1.z); t.w = tf32_rna(ra1.w);
        *(float4*)&As[0][(ar + 64) * 20 + ac] = t;
        t.x = tf32_rna(rb0.x); t.y = tf32_rna(rb0.y); t.z = tf32_rna(rb0.z); t.w = tf32_rna(rb0.w);
        *(float4*)&Bs[0][br * 136 + bc] = t;
        t.x = tf32_rna(rb1.x); t.y = tf32_rna(rb1.y); t.z = tf32_rna(rb1.z); t.w = tf32_rna(rb1.w);
        *(float4*)&Bs[0][(br + 8) * 136 + bc] = t;
    }
    __syncthreads();

    for (int kt = 0; kt < nk; ++kt) {
        const int cur = kt & 1;
        const bool more = (kt + 1) < nk;
        if (more) {
            const int ko = (kt + 1) << 4;
            ra0 = *(const float4*)(Abase + (size_t)ar * K + ko + ac);
            ra1 = *(const float4*)(Abase + (size_t)(ar + 64) * K + ko + ac);
            rb0 = *(const float4*)(Bbase + (size_t)(ko + br) * N + bc);
            rb1 = *(const float4*)(Bbase + (size_t)(ko + br + 8) * N + bc);
        }

#pragma unroll
        for (int kk = 0; kk < 16; kk += 8) {
            uint32_t a[4][4], b[4][2];
#pragma unroll
            for (int mi = 0; mi < 4; mi++) {
                const int r0 = wm * 64 + mi * 16 + g;
                a[mi][0] = __float_as_uint(As[cur][r0 * 20 + kk + tg]);
                a[mi][1] = __float_as_uint(As[cur][(r0 + 8) * 20 + kk + tg]);
                a[mi][2] = __float_as_uint(As[cur][r0 * 20 + kk + tg + 4]);
                a[mi][3] = __float_as_uint(As[cur][(r0 + 8) * 20 + kk + tg + 4]);
            }
#pragma unroll
            for (int ni = 0; ni < 4; ni++) {
                const int c0 = wn * 32 + ni * 8 + g;
                b[ni][0] = __float_as_uint(Bs[cur][(kk + tg) * 136 + c0]);
                b[ni][1] = __float_as_uint(Bs[cur][(kk + tg + 4) * 136 + c0]);
            }
#pragma unroll
            for (int mi = 0; mi < 4; mi++)
#pragma unroll
                for (int ni = 0; ni < 4; ni++)
                    mma_tf32(acc[mi][ni], a[mi], b[ni]);
        }

        if (more) {
            const int nxt = cur ^ 1;
            float4 t;
            t.x = tf32_rna(ra0.x); t.y = tf32_rna(ra0.y); t.z = tf32_rna(ra0.z); t.w = tf32_rna(ra0.w);
            *(float4*)&As[nxt][ar * 20 + ac] = t;
            t.x = tf32_rna(ra1.x); t.y = tf32_rna(ra1.y); t.z = tf32_rna(ra1.z); t.w = tf32_rna(ra1.w);
            *(float4*)&As[nxt][(ar + 64) * 20 + ac] = t;
            t.x = tf32_rna(rb0.x); t.y = tf32_rna(rb0.y); t.z = tf32_rna(rb0.z); t.w = tf32_rna(rb0.w);
            *(float4*)&Bs[nxt][br * 136 + bc] = t;
            t.x = tf32_rna(rb1.x); t.y = tf32_rna(rb1.y); t.z = tf32_rna(rb1.z); t.w = tf32_rna(rb1.w);
            *(float4*)&Bs[nxt][(br + 8) * 136 + bc] = t;
        }
        __syncthreads();
    }

    // epilogue
#pragma unroll
    for (int mi = 0; mi < 4; mi++) {
        const int r = m0 + wm * 64 + mi * 16 + g;
#pragma unroll
        for (int ni = 0; ni < 4; ni++) {
            const int c = n0 + wn * 32 + ni * 8 + 2 * tg;
            float2 lo = make_float2(acc[mi][ni][0], acc[mi][ni][1]);
            float2 hi = make_float2(acc[mi][ni][2], acc[mi][ni][3]);
            *(float2*)&C[(size_t)r * N + c]       = lo;
            *(float2*)&C[(size_t)(r + 8) * N + c] = hi;
        }
    }
}

// ---------------------------------------------------------------------------
// Attention: block = (q-chunk of 64 rows, head, bt). fp32 SIMT.
// q:[4096,3072] (h*64+d cols), kv:[512,6144] (k at h*64+d, v at 3072+h*64+d)
// scores scaled by 1/sqrt(64)=1/8 (= dh^-0.25 applied to both q and k).
// ---------------------------------------------------------------------------
#define QS_STRIDE 68
#define SC_STRIDE 132
#define ATTN_SMEM ((64 * QS_STRIDE + 128 * QS_STRIDE + 64 * SC_STRIDE) * 4)

__global__ __launch_bounds__(256)
void attn_kernel(const float* __restrict__ q, const float* __restrict__ kv,
                 float* __restrict__ ao)
{
    extern __shared__ float sm[];
    float* q_s = sm;                                   // 64 x 68
    float* k_s = sm + 64 * QS_STRIDE;                  // 128 x 68 (then reused for v)
    float* sc  = sm + 64 * QS_STRIDE + 128 * QS_STRIDE; // 64 x 132

    const int tid = threadIdx.x;
    const int cq  = blockIdx.x;
    const int h   = blockIdx.y;
    const int bt  = blockIdx.z;
    const int qr0 = cq * 64;

    const float* qb = q  + ((size_t)bt * HW + qr0) * HIDDEN + h * D_HEAD;
    const float* kb = kv + (size_t)bt * AA * KV_DIM + h * D_HEAD;
    const float* vb = kb + HIDDEN;

    // load q chunk (64x64) and k (128x64)
#pragma unroll
    for (int j = 0; j < 4; j++) {
        const int f = tid + 256 * j;          // 0..1023
        const int r = f >> 4, d4 = f & 15;
        float4 v = *(const float4*)(qb + (size_t)r * HIDDEN + d4 * 4);
        *(float4*)&q_s[r * QS_STRIDE + d4 * 4] = v;
    }
#pragma unroll
    for (int j = 0; j < 8; j++) {
        const int f = tid + 256 * j;          // 0..2047
        const int r = f >> 4, d4 = f & 15;
        float4 v = *(const float4*)(kb + (size_t)r * KV_DIM + d4 * 4);
        *(float4*)&k_s[r * QS_STRIDE + d4 * 4] = v;
    }
    __syncthreads();

    // scores: thread -> 4 q-rows (qg) x 8 keys (kg + 16j)
    {
        const int qg = tid >> 4, kg = tid & 15;
        float acc[4][8];
#pragma unroll
        for (int i = 0; i < 4; i++)
#pragma unroll
            for (int j = 0; j < 8; j++) acc[i][j] = 0.f;

        const float4* q4 = (const float4*)q_s;
        const float4* k4 = (const float4*)k_s;
#pragma unroll 4
        for (int d4 = 0; d4 < 16; d4++) {
            float4 qv[4], kk[8];
#pragma unroll
            for (int i = 0; i < 4; i++) qv[i] = q4[(qg * 4 + i) * 17 + d4];
#pragma unroll
            for (int j = 0; j < 8; j++) kk[j] = k4[(kg + 16 * j) * 17 + d4];
#pragma unroll
            for (int i = 0; i < 4; i++)
#pragma unroll
                for (int j = 0; j < 8; j++)
                    acc[i][j] += qv[i].x * kk[j].x + qv[i].y * kk[j].y
                               + qv[i].z * kk[j].z + qv[i].w * kk[j].w;
        }
#pragma unroll
        for (int i = 0; i < 4; i++)
#pragma unroll
            for (int j = 0; j < 8; j++)
                sc[(qg * 4 + i) * SC_STRIDE + kg + 16 * j] = acc[i][j] * 0.125f;
    }
    __syncthreads();

    // overwrite k_s with v
#pragma unroll
    for (int j = 0; j < 8; j++) {
        const int f = tid + 256 * j;
        const int r = f >> 4, d4 = f & 15;
        float4 v = *(const float4*)(vb + (size_t)r * KV_DIM + d4 * 4);
        *(float4*)&k_s[r * QS_STRIDE + d4 * 4] = v;
    }

    // softmax: 4 threads per row (quad-cooperative)
    {
        const int row = tid >> 2, part = tid & 3;
        float* srow = sc + row * SC_STRIDE + part;   // stride-4 scan
        float mx = -FLT_MAX;
#pragma unroll
        for (int j = 0; j < 32; j++) mx = fmaxf(mx, srow[j * 4]);
        mx = fmaxf(mx, __shfl_xor_sync(0xffffffffu, mx, 1));
        mx = fmaxf(mx, __shfl_xor_sync(0xffffffffu, mx, 2));
        float s = 0.f;
#pragma unroll
        for (int j = 0; j < 32; j++) {
            float e = __expf(srow[j * 4] - mx);
            srow[j * 4] = e;
            s += e;
        }
        s += __shfl_xor_sync(0xffffffffu, s, 1);
        s += __shfl_xor_sync(0xffffffffu, s, 2);
        const float inv = 1.0f / s;
#pragma unroll
        for (int j = 0; j < 32; j++) srow[j * 4] *= inv;
    }
    __syncthreads();

    // PV: thread -> 4 q-rows (qg) x 4 d (dg float4)
    {
        const int qg = tid >> 4, dg = tid & 15;
        float4 acc[4];
#pragma unroll
        for (int i = 0; i < 4; i++) acc[i] = make_float4(0.f, 0.f, 0.f, 0.f);
        const float4* v4 = (const float4*)k_s;
#pragma unroll 4
        for (int k = 0; k < 128; k++) {
            float4 vv = v4[k * 17 + dg];
#pragma unroll
            for (int i = 0; i < 4; i++) {
                const float p = sc[(qg * 4 + i) * SC_STRIDE + k];
                acc[i].x += p * vv.x; acc[i].y += p * vv.y;
                acc[i].z += p * vv.z; acc[i].w += p * vv.w;
            }
        }
#pragma unroll
        for (int i = 0; i < 4; i++) {
            float* dst = ao + ((size_t)bt * HW + qr0 + qg * 4 + i) * HIDDEN + h * D_HEAD + dg * 4;
            *(float4*)dst = acc[i];
        }
    }
}

// ---------------------------------------------------------------------------
// Launch
// ---------------------------------------------------------------------------
extern "C" void kernel_launch(void* const* d_in, const int* in_sizes, int n_in,
                              void* d_out, int out_size)
{
    const float* x       = (const float*)d_in[0];
    const float* latents = (const float*)d_in[1];
    const float* g1      = (const float*)d_in[2];
    const float* b1      = (const float*)d_in[3];
    const float* g2      = (const float*)d_in[4];
    const float* b2      = (const float*)d_in[5];
    const float* Wq      = (const float*)d_in[6];
    const float* Wkv     = (const float*)d_in[7];
    const float* Wo      = (const float*)d_in[8];
    float* out           = (float*)d_out;

    float *xn, *ln, *q, *kvb, *ao;
    cudaGetSymbolAddress((void**)&xn,  g_xn);
    cudaGetSymbolAddress((void**)&ln,  g_ln);
    cudaGetSymbolAddress((void**)&q,   g_q);
    cudaGetSymbolAddress((void**)&kvb, g_kv);
    cudaGetSymbolAddress((void**)&ao,  g_ao);

    cudaFuncSetAttribute(attn_kernel, cudaFuncAttributeMaxDynamicSharedMemorySize, ATTN_SMEM);

    ln_kernel<<<ROWS_X, 256>>>(x, g1, b1, xn);
    ln_kernel<<<ROWS_L, 256>>>(latents, g2, b2, ln);

    gemm_tf32<<<dim3(HIDDEN / 128, ROWS_L / 128), 256>>>(ln, Wq, q, ROWS_L, HIDDEN, C_DIM);
    gemm_tf32<<<dim3(KV_DIM / 128, ROWS_X / 128), 256>>>(xn, Wkv, kvb, ROWS_X, KV_DIM, C_DIM);

    attn_kernel<<<dim3(HW / 64, N_HEADS, BT), 256, ATTN_SMEM>>>(q, kvb, ao);

    gemm_tf32<<<dim3(C_DIM / 128, ROWS_L / 128), 256>>>(ao, Wo, out, ROWS_L, C_DIM, HIDDEN);
}

// round 6
// speedup vs baseline: 1.0984x; 1.0984x over previous
#include <cuda_runtime.h>
#include <cuda_bf16.h>
#include <cstdint>
#include <cfloat>

// ---------------------------------------------------------------------------
// Problem dims (fixed)
// ---------------------------------------------------------------------------
#define C_DIM   3072
#define HIDDEN  3072
#define KV_DIM  6144
#define N_HEADS 48
#define D_HEAD  64
#define BT      4
#define AA      128
#define HW      1024
#define ROWS_X  (BT * AA)    // 512
#define ROWS_L  (BT * HW)    // 4096

// ---------------------------------------------------------------------------
// Scratch (device globals: allocation-free rule)
// ---------------------------------------------------------------------------
__device__ float g_xn [ROWS_X * C_DIM];
__device__ float g_ln [ROWS_L * C_DIM];
__device__ float g_q  [ROWS_L * HIDDEN];
__device__ float g_kv [ROWS_X * KV_DIM];
__device__ float g_ao [ROWS_L * HIDDEN];
__device__ float g_wq [C_DIM * HIDDEN];     // tf32-rounded copies (original layout)
__device__ float g_wkv[C_DIM * KV_DIM];
__device__ float g_wo [HIDDEN * C_DIM];

// ---------------------------------------------------------------------------
// Helpers (sm_100-safe: mma.sync + cp.async only, no tcgen05)
// ---------------------------------------------------------------------------
__device__ __forceinline__ float tf32_rna(float x) {
    uint32_t u;
    asm("cvt.rna.tf32.f32 %0, %1;" : "=r"(u) : "f"(x));
    return __uint_as_float(u);
}

__device__ __forceinline__ uint32_t smem_u32(const void* p) {
    uint32_t a;
    asm("{ .reg .u64 t; cvta.to.shared.u64 t, %1; cvt.u32.u64 %0, t; }" : "=r"(a) : "l"(p));
    return a;
}

__device__ __forceinline__ void mma_tf32(float* c, const uint32_t* a, const uint32_t* b) {
    asm volatile(
        "mma.sync.aligned.m16n8k8.row.col.f32.tf32.tf32.f32 "
        "{%0,%1,%2,%3}, {%4,%5,%6,%7}, {%8,%9}, {%0,%1,%2,%3};\n"
        : "+f"(c[0]), "+f"(c[1]), "+f"(c[2]), "+f"(c[3])
        : "r"(a[0]), "r"(a[1]), "r"(a[2]), "r"(a[3]), "r"(b[0]), "r"(b[1]));
}

__device__ __forceinline__ void cpa16(uint32_t dst, const void* src) {
    asm volatile("cp.async.cg.shared.global [%0], [%1], 16;\n" :: "r"(dst), "l"(src) : "memory");
}
#define CP_COMMIT() asm volatile("cp.async.commit_group;\n" ::: "memory")
#define CP_WAIT1()  asm volatile("cp.async.wait_group 1;\n" ::: "memory")

// ---------------------------------------------------------------------------
// LayerNorm (outputs tf32-rounded: they only feed tensor-core GEMMs)
// ---------------------------------------------------------------------------
__global__ __launch_bounds__(256)
void ln_kernel(const float* __restrict__ x, const float* __restrict__ gamma,
               const float* __restrict__ beta, float* __restrict__ y)
{
    const int row = blockIdx.x;
    const int tid = threadIdx.x;
    const float* xr = x + (size_t)row * C_DIM;
    float*       yr = y + (size_t)row * C_DIM;

    float4 v[3];
    float s = 0.f, s2 = 0.f;
#pragma unroll
    for (int j = 0; j < 3; j++) {
        v[j] = *(const float4*)(xr + (size_t)(tid + 256 * j) * 4);
        s  += v[j].x + v[j].y + v[j].z + v[j].w;
        s2 += v[j].x*v[j].x + v[j].y*v[j].y + v[j].z*v[j].z + v[j].w*v[j].w;
    }
#pragma unroll
    for (int o = 16; o > 0; o >>= 1) {
        s  += __shfl_xor_sync(0xffffffffu, s, o);
        s2 += __shfl_xor_sync(0xffffffffu, s2, o);
    }
    __shared__ float red[2][8];
    const int w = tid >> 5, lane = tid & 31;
    if (lane == 0) { red[0][w] = s; red[1][w] = s2; }
    __syncthreads();
    float ts = 0.f, ts2 = 0.f;
#pragma unroll
    for (int i = 0; i < 8; i++) { ts += red[0][i]; ts2 += red[1][i]; }
    const float mean = ts * (1.0f / C_DIM);
    const float var  = ts2 * (1.0f / C_DIM) - mean * mean;
    const float rstd = rsqrtf(var + 1e-5f);

#pragma unroll
    for (int j = 0; j < 3; j++) {
        const int c4 = (tid + 256 * j) * 4;
        float4 g = *(const float4*)(gamma + c4);
        float4 b = *(const float4*)(beta  + c4);
        float4 o;
        o.x = tf32_rna((v[j].x - mean) * rstd * g.x + b.x);
        o.y = tf32_rna((v[j].y - mean) * rstd * g.y + b.y);
        o.z = tf32_rna((v[j].z - mean) * rstd * g.z + b.z);
        o.w = tf32_rna((v[j].w - mean) * rstd * g.w + b.w);
        *(float4*)(yr + c4) = o;
    }
}

// ---------------------------------------------------------------------------
// Elementwise tf32 pre-round copy (weights keep original [K,N] layout)
// ---------------------------------------------------------------------------
__global__ __launch_bounds__(256)
void round_copy(const float* __restrict__ in, float* __restrict__ out)
{
    const size_t i = ((size_t)blockIdx.x * 256 + threadIdx.x) * 4;
    float4 v = *(const float4*)(in + i);
    v.x = tf32_rna(v.x); v.y = tf32_rna(v.y);
    v.z = tf32_rna(v.z); v.w = tf32_rna(v.w);
    *(float4*)(out + i) = v;
}

// ---------------------------------------------------------------------------
// TF32 GEMM v2: C[M,N] = A[M,K] * B[K,N], row-major, operands pre-rounded.
// 128x128x16 tile, 256 threads (8 warps 2m x 4n, warp tile 64x32),
// 3-stage cp.async pipeline, dynamic smem. M%128==0, N%128==0, K%16==0.
// ---------------------------------------------------------------------------
#define BMT 128
#define BNT 128
#define BKT 16
#define A_STRIDE 20            // floats per A smem row (pad vs 16)
#define B_STRIDE 136           // floats per B smem row (pad vs 128)
#define A_STG (BMT * A_STRIDE) // 2560 floats
#define B_STG (BKT * B_STRIDE) // 2176 floats
#define G2_SMEM ((3 * (A_STG + B_STG)) * 4)   // 56832 B

__global__ __launch_bounds__(256, 2)
void gemm_tf32p(const float* __restrict__ A, const float* __restrict__ B,
                float* __restrict__ C, int M, int N, int K)
{
    extern __shared__ float smf[];
    const uint32_t sbase = smem_u32(smf);

    const int tid  = threadIdx.x;
    const int lane = tid & 31;
    const int w    = tid >> 5;
    const int wm   = w >> 2;          // 0..1
    const int wn   = w & 3;           // 0..3
    const int g    = lane >> 2;       // 0..7
    const int tg   = lane & 3;        // 0..3
    const int m0   = blockIdx.x * BMT;
    const int n0   = blockIdx.y * BNT;

    const int nk = K / BKT;

    // staging maps: A: tid-> (row, 16B chunk); two per thread. B likewise.
    const int arow = tid >> 2, acol = tid & 3;    // rows 0..63 (+64), chunk 0..3
    const int brow = tid >> 5, bcol = tid & 31;   // rows 0..7 (+8), chunk 0..31

    auto fill = [&](int s, int kc) {
        const uint32_t aoff = sbase + (uint32_t)s * (A_STG * 4);
        const uint32_t boff = sbase + (uint32_t)(3 * A_STG + s * B_STG) * 4;
        cpa16(aoff + arow * (A_STRIDE * 4) + acol * 16,
              A + (size_t)(m0 + arow) * K + kc + acol * 4);
        cpa16(aoff + (arow + 64) * (A_STRIDE * 4) + acol * 16,
              A + (size_t)(m0 + arow + 64) * K + kc + acol * 4);
        cpa16(boff + brow * (B_STRIDE * 4) + bcol * 16,
              B + (size_t)(kc + brow) * N + n0 + bcol * 4);
        cpa16(boff + (brow + 8) * (B_STRIDE * 4) + bcol * 16,
              B + (size_t)(kc + brow + 8) * N + n0 + bcol * 4);
        CP_COMMIT();
    };

    float acc[4][4][4];
#pragma unroll
    for (int mi = 0; mi < 4; mi++)
#pragma unroll
        for (int ni = 0; ni < 4; ni++)
#pragma unroll
            for (int r = 0; r < 4; r++) acc[mi][ni][r] = 0.f;

    fill(0, 0);
    fill(1, BKT);

    for (int kt = 0; kt < nk; ++kt) {
        CP_WAIT1();
        __syncthreads();

        if (kt + 2 < nk) fill((kt + 2) % 3, (kt + 2) * BKT);
        else             CP_COMMIT();   // empty group keeps wait counts aligned

        const int s = kt % 3;
        const float* As = smf + s * A_STG;
        const float* Bs = smf + 3 * A_STG + s * B_STG;

#pragma unroll
        for (int kk = 0; kk < 16; kk += 8) {
            uint32_t a[4][4], b[4][2];
#pragma unroll
            for (int mi = 0; mi < 4; mi++) {
                const int r0 = wm * 64 + mi * 16 + g;
                a[mi][0] = __float_as_uint(As[r0 * A_STRIDE + kk + tg]);
                a[mi][1] = __float_as_uint(As[(r0 + 8) * A_STRIDE + kk + tg]);
                a[mi][2] = __float_as_uint(As[r0 * A_STRIDE + kk + tg + 4]);
                a[mi][3] = __float_as_uint(As[(r0 + 8) * A_STRIDE + kk + tg + 4]);
            }
#pragma unroll
            for (int ni = 0; ni < 4; ni++) {
                const int c0 = wn * 32 + ni * 8 + g;
                b[ni][0] = __float_as_uint(Bs[(kk + tg) * B_STRIDE + c0]);
                b[ni][1] = __float_as_uint(Bs[(kk + tg + 4) * B_STRIDE + c0]);
            }
#pragma unroll
            for (int mi = 0; mi < 4; mi++)
#pragma unroll
                for (int ni = 0; ni < 4; ni++)
                    mma_tf32(acc[mi][ni], a[mi], b[ni]);
        }
    }

    // epilogue
#pragma unroll
    for (int mi = 0; mi < 4; mi++) {
        const int r = m0 + wm * 64 + mi * 16 + g;
#pragma unroll
        for (int ni = 0; ni < 4; ni++) {
            const int c = n0 + wn * 32 + ni * 8 + 2 * tg;
            float2 lo = make_float2(acc[mi][ni][0], acc[mi][ni][1]);
            float2 hi = make_float2(acc[mi][ni][2], acc[mi][ni][3]);
            *(float2*)&C[(size_t)r * N + c]       = lo;
            *(float2*)&C[(size_t)(r + 8) * N + c] = hi;
        }
    }
}

// ---------------------------------------------------------------------------
// Attention (R1-proven fp32 core; output tf32-rounded for the Wo GEMM)
// ---------------------------------------------------------------------------
#define QS_STRIDE 68
#define SC_STRIDE 132
#define ATTN_SMEM ((64 * QS_STRIDE + 128 * QS_STRIDE + 64 * SC_STRIDE) * 4)

__global__ __launch_bounds__(256)
void attn_kernel(const float* __restrict__ q, const float* __restrict__ kv,
                 float* __restrict__ ao)
{
    extern __shared__ float sm[];
    float* q_s = sm;                                    // 64 x 68
    float* k_s = sm + 64 * QS_STRIDE;                   // 128 x 68 (then v)
    float* sc  = sm + 64 * QS_STRIDE + 128 * QS_STRIDE; // 64 x 132

    const int tid = threadIdx.x;
    const int cq  = blockIdx.x;
    const int h   = blockIdx.y;
    const int bt  = blockIdx.z;
    const int qr0 = cq * 64;

    const float* qb = q  + ((size_t)bt * HW + qr0) * HIDDEN + h * D_HEAD;
    const float* kb = kv + (size_t)bt * AA * KV_DIM + h * D_HEAD;
    const float* vb = kb + HIDDEN;

#pragma unroll
    for (int j = 0; j < 4; j++) {
        const int f = tid + 256 * j;
        const int r = f >> 4, d4 = f & 15;
        float4 v = *(const float4*)(qb + (size_t)r * HIDDEN + d4 * 4);
        *(float4*)&q_s[r * QS_STRIDE + d4 * 4] = v;
    }
#pragma unroll
    for (int j = 0; j < 8; j++) {
        const int f = tid + 256 * j;
        const int r = f >> 4, d4 = f & 15;
        float4 v = *(const float4*)(kb + (size_t)r * KV_DIM + d4 * 4);
        *(float4*)&k_s[r * QS_STRIDE + d4 * 4] = v;
    }
    __syncthreads();

    // scores: thread -> 4 q-rows (qg) x 8 keys (kg + 16j)
    {
        const int qg = tid >> 4, kg = tid & 15;
        float acc[4][8];
#pragma unroll
        for (int i = 0; i < 4; i++)
#pragma unroll
            for (int j = 0; j < 8; j++) acc[i][j] = 0.f;

        const float4* q4 = (const float4*)q_s;
        const float4* k4 = (const float4*)k_s;
#pragma unroll 4
        for (int d4 = 0; d4 < 16; d4++) {
            float4 qv[4], kk[8];
#pragma unroll
            for (int i = 0; i < 4; i++) qv[i] = q4[(qg * 4 + i) * 17 + d4];
#pragma unroll
            for (int j = 0; j < 8; j++) kk[j] = k4[(kg + 16 * j) * 17 + d4];
#pragma unroll
            for (int i = 0; i < 4; i++)
#pragma unroll
                for (int j = 0; j < 8; j++)
                    acc[i][j] += qv[i].x * kk[j].x + qv[i].y * kk[j].y
                               + qv[i].z * kk[j].z + qv[i].w * kk[j].w;
        }
#pragma unroll
        for (int i = 0; i < 4; i++)
#pragma unroll
            for (int j = 0; j < 8; j++)
                sc[(qg * 4 + i) * SC_STRIDE + kg + 16 * j] = acc[i][j] * 0.125f;
    }
    __syncthreads();

    // overwrite k_s with v
#pragma unroll
    for (int j = 0; j < 8; j++) {
        const int f = tid + 256 * j;
        const int r = f >> 4, d4 = f & 15;
        float4 v = *(const float4*)(vb + (size_t)r * KV_DIM + d4 * 4);
        *(float4*)&k_s[r * QS_STRIDE + d4 * 4] = v;
    }

    // softmax: 4 threads per row
    {
        const int row = tid >> 2, part = tid & 3;
        float* srow = sc + row * SC_STRIDE + part;
        float mx = -FLT_MAX;
#pragma unroll
        for (int j = 0; j < 32; j++) mx = fmaxf(mx, srow[j * 4]);
        mx = fmaxf(mx, __shfl_xor_sync(0xffffffffu, mx, 1));
        mx = fmaxf(mx, __shfl_xor_sync(0xffffffffu, mx, 2));
        float s = 0.f;
#pragma unroll
        for (int j = 0; j < 32; j++) {
            float e = __expf(srow[j * 4] - mx);
            srow[j * 4] = e;
            s += e;
        }
        s += __shfl_xor_sync(0xffffffffu, s, 1);
        s += __shfl_xor_sync(0xffffffffu, s, 2);
        const float inv = 1.0f / s;
#pragma unroll
        for (int j = 0; j < 32; j++) srow[j * 4] *= inv;
    }
    __syncthreads();

    // PV: thread -> 4 q-rows (qg) x 4 d (dg float4)
    {
        const int qg = tid >> 4, dg = tid & 15;
        float4 acc[4];
#pragma unroll
        for (int i = 0; i < 4; i++) acc[i] = make_float4(0.f, 0.f, 0.f, 0.f);
        const float4* v4 = (const float4*)k_s;
#pragma unroll 4
        for (int k = 0; k < 128; k++) {
            float4 vv = v4[k * 17 + dg];
#pragma unroll
            for (int i = 0; i < 4; i++) {
                const float p = sc[(qg * 4 + i) * SC_STRIDE + k];
                acc[i].x += p * vv.x; acc[i].y += p * vv.y;
                acc[i].z += p * vv.z; acc[i].w += p * vv.w;
            }
        }
#pragma unroll
        for (int i = 0; i < 4; i++) {
            float4 o;
            o.x = tf32_rna(acc[i].x); o.y = tf32_rna(acc[i].y);
            o.z = tf32_rna(acc[i].z); o.w = tf32_rna(acc[i].w);
            float* dst = ao + ((size_t)bt * HW + qr0 + qg * 4 + i) * HIDDEN + h * D_HEAD + dg * 4;
            *(float4*)dst = o;
        }
    }
}

// ---------------------------------------------------------------------------
// Launch
// ---------------------------------------------------------------------------
extern "C" void kernel_launch(void* const* d_in, const int* in_sizes, int n_in,
                              void* d_out, int out_size)
{
    const float* x       = (const float*)d_in[0];
    const float* latents = (const float*)d_in[1];
    const float* g1      = (const float*)d_in[2];
    const float* b1      = (const float*)d_in[3];
    const float* g2      = (const float*)d_in[4];
    const float* b2      = (const float*)d_in[5];
    const float* Wq      = (const float*)d_in[6];
    const float* Wkv     = (const float*)d_in[7];
    const float* Wo      = (const float*)d_in[8];
    float* out           = (float*)d_out;

    float *xn, *ln, *q, *kvb, *ao, *wq, *wkv, *wo;
    cudaGetSymbolAddress((void**)&xn,  g_xn);
    cudaGetSymbolAddress((void**)&ln,  g_ln);
    cudaGetSymbolAddress((void**)&q,   g_q);
    cudaGetSymbolAddress((void**)&kvb, g_kv);
    cudaGetSymbolAddress((void**)&ao,  g_ao);
    cudaGetSymbolAddress((void**)&wq,  g_wq);
    cudaGetSymbolAddress((void**)&wkv, g_wkv);
    cudaGetSymbolAddress((void**)&wo,  g_wo);

    cudaFuncSetAttribute(gemm_tf32p,  cudaFuncAttributeMaxDynamicSharedMemorySize, G2_SMEM);
    cudaFuncSetAttribute(attn_kernel, cudaFuncAttributeMaxDynamicSharedMemorySize, ATTN_SMEM);

    // tf32 pre-round of weights (original [K,N] layout)
    round_copy<<<(C_DIM * (size_t)HIDDEN) / 1024, 256>>>(Wq,  wq);
    round_copy<<<(C_DIM * (size_t)KV_DIM) / 1024, 256>>>(Wkv, wkv);
    round_copy<<<((size_t)HIDDEN * C_DIM) / 1024, 256>>>(Wo,  wo);

    ln_kernel<<<ROWS_X, 256>>>(x, g1, b1, xn);
    ln_kernel<<<ROWS_L, 256>>>(latents, g2, b2, ln);

    gemm_tf32p<<<dim3(ROWS_L / BMT, HIDDEN / BNT), 256, G2_SMEM>>>(ln, wq,  q,   ROWS_L, HIDDEN, C_DIM);
    gemm_tf32p<<<dim3(ROWS_X / BMT, KV_DIM / BNT), 256, G2_SMEM>>>(xn, wkv, kvb, ROWS_X, KV_DIM, C_DIM);

    attn_kernel<<<dim3(HW / 64, N_HEADS, BT), 256, ATTN_SMEM>>>(q, kvb, ao);

    gemm_tf32p<<<dim3(ROWS_L / BMT, C_DIM / BNT), 256, G2_SMEM>>>(ao, wo, out, ROWS_L, C_DIM, HIDDEN);
}

// round 7
// speedup vs baseline: 1.6901x; 1.5387x over previous
#include <cuda_runtime.h>
#include <cuda_fp16.h>
#include <cstdint>
#include <cfloat>

// ---------------------------------------------------------------------------
// Problem dims (fixed)
// ---------------------------------------------------------------------------
#define C_DIM   3072
#define HIDDEN  3072
#define KV_DIM  6144
#define N_HEADS 48
#define D_HEAD  64
#define BT      4
#define AA      128
#define HW      1024
#define ROWS_X  (BT * AA)    // 512
#define ROWS_L  (BT * HW)    // 4096

// ---------------------------------------------------------------------------
// Scratch (device globals: allocation-free rule)
// ---------------------------------------------------------------------------
__device__ __half g_xnh[ROWS_X * C_DIM];
__device__ __half g_lnh[ROWS_L * C_DIM];
__device__ float  g_q  [ROWS_L * HIDDEN];
__device__ float  g_kv [ROWS_X * KV_DIM];
__device__ __half g_aoh[ROWS_L * HIDDEN];
__device__ __half g_wqh [HIDDEN * C_DIM];   // WqT  half [N=3072][K=3072]
__device__ __half g_wkvh[KV_DIM * C_DIM];   // WkvT half [N=6144][K=3072]
__device__ __half g_woh [C_DIM * HIDDEN];   // WoT  half [N=3072][K=3072]

// ---------------------------------------------------------------------------
// Helpers (sm_100-safe: mma.sync fp16 + cp.async only)
// ---------------------------------------------------------------------------
__device__ __forceinline__ void mma_f16(float* c, const uint32_t* a, const uint32_t* b) {
    asm volatile(
        "mma.sync.aligned.m16n8k16.row.col.f32.f16.f16.f32 "
        "{%0,%1,%2,%3}, {%4,%5,%6,%7}, {%8,%9}, {%0,%1,%2,%3};\n"
        : "+f"(c[0]), "+f"(c[1]), "+f"(c[2]), "+f"(c[3])
        : "r"(a[0]), "r"(a[1]), "r"(a[2]), "r"(a[3]), "r"(b[0]), "r"(b[1]));
}

__device__ __forceinline__ uint32_t smem_u32(const void* p) {
    uint32_t a;
    asm("{ .reg .u64 t; cvta.to.shared.u64 t, %1; cvt.u32.u64 %0, t; }" : "=r"(a) : "l"(p));
    return a;
}

__device__ __forceinline__ void cpa16(uint32_t dst, const void* src) {
    asm volatile("cp.async.cg.shared.global [%0], [%1], 16;\n" :: "r"(dst), "l"(src) : "memory");
}
#define CP_COMMIT() asm volatile("cp.async.commit_group;\n" ::: "memory")
#define CP_WAIT1()  asm volatile("cp.async.wait_group 1;\n" ::: "memory")

// ---------------------------------------------------------------------------
// LayerNorm: fp32 math, writes fp16 (only feeds fp16 tensor-core GEMMs)
// ---------------------------------------------------------------------------
__global__ __launch_bounds__(256)
void ln_kernel(const float* __restrict__ x, const float* __restrict__ gamma,
               const float* __restrict__ beta, __half* __restrict__ y)
{
    const int row = blockIdx.x;
    const int tid = threadIdx.x;
    const float* xr = x + (size_t)row * C_DIM;
    __half*      yr = y + (size_t)row * C_DIM;

    float4 v[3];
    float s = 0.f, s2 = 0.f;
#pragma unroll
    for (int j = 0; j < 3; j++) {
        v[j] = *(const float4*)(xr + (size_t)(tid + 256 * j) * 4);
        s  += v[j].x + v[j].y + v[j].z + v[j].w;
        s2 += v[j].x*v[j].x + v[j].y*v[j].y + v[j].z*v[j].z + v[j].w*v[j].w;
    }
#pragma unroll
    for (int o = 16; o > 0; o >>= 1) {
        s  += __shfl_xor_sync(0xffffffffu, s, o);
        s2 += __shfl_xor_sync(0xffffffffu, s2, o);
    }
    __shared__ float red[2][8];
    const int w = tid >> 5, lane = tid & 31;
    if (lane == 0) { red[0][w] = s; red[1][w] = s2; }
    __syncthreads();
    float ts = 0.f, ts2 = 0.f;
#pragma unroll
    for (int i = 0; i < 8; i++) { ts += red[0][i]; ts2 += red[1][i]; }
    const float mean = ts * (1.0f / C_DIM);
    const float var  = ts2 * (1.0f / C_DIM) - mean * mean;
    const float rstd = rsqrtf(var + 1e-5f);

#pragma unroll
    for (int j = 0; j < 3; j++) {
        const int c4 = (tid + 256 * j) * 4;
        float4 g = *(const float4*)(gamma + c4);
        float4 b = *(const float4*)(beta  + c4);
        __half2 h0 = __floats2half2_rn((v[j].x - mean) * rstd * g.x + b.x,
                                       (v[j].y - mean) * rstd * g.y + b.y);
        __half2 h1 = __floats2half2_rn((v[j].z - mean) * rstd * g.z + b.z,
                                       (v[j].w - mean) * rstd * g.w + b.w);
        uint2 o;
        o.x = *(uint32_t*)&h0;
        o.y = *(uint32_t*)&h1;
        *(uint2*)(yr + c4) = o;
    }
}

// ---------------------------------------------------------------------------
// Transpose+convert: W[K][N] fp32 -> WT[N][K] fp16
// ---------------------------------------------------------------------------
__global__ __launch_bounds__(256)
void transpose_h(const float* __restrict__ W, __half* __restrict__ WT, int K, int N)
{
    __shared__ float t[32][33];
    const int tx = threadIdx.x, ty = threadIdx.y;
    const int n = blockIdx.x * 32 + tx;
    const int k = blockIdx.y * 32 + ty;
#pragma unroll
    for (int j = 0; j < 32; j += 8)
        t[ty + j][tx] = W[(size_t)(k + j) * N + n];
    __syncthreads();
    const int n2 = blockIdx.x * 32 + ty;
    const int k2 = blockIdx.y * 32 + tx;
#pragma unroll
    for (int j = 0; j < 32; j += 8)
        WT[(size_t)(n2 + j) * K + k2] = __float2half_rn(t[tx][ty + j]);
}

// ---------------------------------------------------------------------------
// FP16 GEMM: C[M,N] fp32 = A[M,K] half (row-major) * Bt[N,K] half ^T
// 128x128 block, BK=32, 8 warps (2m x 4n, warp tile 64x32),
// mma.m16n8k16, 3-stage cp.async. M%128==0, N%128==0, K%32==0.
// ---------------------------------------------------------------------------
#define BMT 128
#define BNT 128
#define BKT 32
#define A_STRH 40                       // halves per A smem row (32 + 8 pad)
#define STG_H  (128 * A_STRH)           // 5120 halves per tile (A or B)
#define STG_B  (STG_H * 2)              // 10240 bytes
#define G2_SMEM (3 * 2 * STG_B)         // 61440 B

__global__ __launch_bounds__(256, 2)
void gemm_f16(const __half* __restrict__ A, const __half* __restrict__ Bt,
              float* __restrict__ C, int M, int N, int K)
{
    extern __shared__ __half smh[];
    const uint32_t sbase = smem_u32(smh);

    const int tid  = threadIdx.x;
    const int lane = tid & 31;
    const int w    = tid >> 5;
    const int wm   = w >> 2;          // 0..1
    const int wn   = w & 3;           // 0..3
    const int g    = lane >> 2;       // 0..7
    const int tg   = lane & 3;        // 0..3
    const int m0   = blockIdx.x * BMT;
    const int n0   = blockIdx.y * BNT;

    const int nk = K / BKT;

    // staging: tile rows (128) x 4 chunks of 16B; thread does rows tid>>2, +64
    const int srow = tid >> 2, schk = tid & 3;

    auto fill = [&](int s, int kc) {
        const uint32_t aoff = sbase + (uint32_t)s * STG_B;
        const uint32_t boff = sbase + (uint32_t)(3 + s) * STG_B;
        cpa16(aoff + srow * (A_STRH * 2) + schk * 16,
              A + (size_t)(m0 + srow) * K + kc + schk * 8);
        cpa16(aoff + (srow + 64) * (A_STRH * 2) + schk * 16,
              A + (size_t)(m0 + srow + 64) * K + kc + schk * 8);
        cpa16(boff + srow * (A_STRH * 2) + schk * 16,
              Bt + (size_t)(n0 + srow) * K + kc + schk * 8);
        cpa16(boff + (srow + 64) * (A_STRH * 2) + schk * 16,
              Bt + (size_t)(n0 + srow + 64) * K + kc + schk * 8);
        CP_COMMIT();
    };

    float acc[4][4][4];
#pragma unroll
    for (int mi = 0; mi < 4; mi++)
#pragma unroll
        for (int ni = 0; ni < 4; ni++)
#pragma unroll
            for (int r = 0; r < 4; r++) acc[mi][ni][r] = 0.f;

    fill(0, 0);
    fill(1, BKT);

    for (int kt = 0; kt < nk; ++kt) {
        CP_WAIT1();
        __syncthreads();

        if (kt + 2 < nk) fill((kt + 2) % 3, (kt + 2) * BKT);
        else             CP_COMMIT();   // empty group keeps wait counts aligned

        const int s = kt % 3;
        const __half* As = smh + s * STG_H;
        const __half* Bs = smh + (3 + s) * STG_H;

#pragma unroll
        for (int k0 = 0; k0 < 32; k0 += 16) {
            uint32_t a[4][4], b[4][2];
#pragma unroll
            for (int mi = 0; mi < 4; mi++) {
                const int r0 = wm * 64 + mi * 16 + g;
                a[mi][0] = *(const uint32_t*)&As[r0 * A_STRH + k0 + 2 * tg];
                a[mi][1] = *(const uint32_t*)&As[(r0 + 8) * A_STRH + k0 + 2 * tg];
                a[mi][2] = *(const uint32_t*)&As[r0 * A_STRH + k0 + 2 * tg + 8];
                a[mi][3] = *(const uint32_t*)&As[(r0 + 8) * A_STRH + k0 + 2 * tg + 8];
            }
#pragma unroll
            for (int ni = 0; ni < 4; ni++) {
                const int nr = wn * 32 + ni * 8 + g;
                b[ni][0] = *(const uint32_t*)&Bs[nr * A_STRH + k0 + 2 * tg];
                b[ni][1] = *(const uint32_t*)&Bs[nr * A_STRH + k0 + 2 * tg + 8];
            }
#pragma unroll
            for (int mi = 0; mi < 4; mi++)
#pragma unroll
                for (int ni = 0; ni < 4; ni++)
                    mma_f16(acc[mi][ni], a[mi], b[ni]);
        }
    }

    // epilogue (same accumulator layout as m16n8k8: c0,c1 @ (g,2tg); c2,c3 @ (g+8,2tg))
#pragma unroll
    for (int mi = 0; mi < 4; mi++) {
        const int r = m0 + wm * 64 + mi * 16 + g;
#pragma unroll
        for (int ni = 0; ni < 4; ni++) {
            const int c = n0 + wn * 32 + ni * 8 + 2 * tg;
            float2 lo = make_float2(acc[mi][ni][0], acc[mi][ni][1]);
            float2 hi = make_float2(acc[mi][ni][2], acc[mi][ni][3]);
            *(float2*)&C[(size_t)r * N + c]       = lo;
            *(float2*)&C[(size_t)(r + 8) * N + c] = hi;
        }
    }
}

// ---------------------------------------------------------------------------
// Attention (R1/R6-proven fp32 core; output fp16 for the Wo GEMM)
// ---------------------------------------------------------------------------
#define QS_STRIDE 68
#define SC_STRIDE 132
#define ATTN_SMEM ((64 * QS_STRIDE + 128 * QS_STRIDE + 64 * SC_STRIDE) * 4)

__global__ __launch_bounds__(256)
void attn_kernel(const float* __restrict__ q, const float* __restrict__ kv,
                 __half* __restrict__ ao)
{
    extern __shared__ float sm[];
    float* q_s = sm;                                    // 64 x 68
    float* k_s = sm + 64 * QS_STRIDE;                   // 128 x 68 (then v)
    float* sc  = sm + 64 * QS_STRIDE + 128 * QS_STRIDE; // 64 x 132

    const int tid = threadIdx.x;
    const int cq  = blockIdx.x;
    const int h   = blockIdx.y;
    const int bt  = blockIdx.z;
    const int qr0 = cq * 64;

    const float* qb = q  + ((size_t)bt * HW + qr0) * HIDDEN + h * D_HEAD;
    const float* kb = kv + (size_t)bt * AA * KV_DIM + h * D_HEAD;
    const float* vb = kb + HIDDEN;

#pragma unroll
    for (int j = 0; j < 4; j++) {
        const int f = tid + 256 * j;
        const int r = f >> 4, d4 = f & 15;
        float4 v = *(const float4*)(qb + (size_t)r * HIDDEN + d4 * 4);
        *(float4*)&q_s[r * QS_STRIDE + d4 * 4] = v;
    }
#pragma unroll
    for (int j = 0; j < 8; j++) {
        const int f = tid + 256 * j;
        const int r = f >> 4, d4 = f & 15;
        float4 v = *(const float4*)(kb + (size_t)r * KV_DIM + d4 * 4);
        *(float4*)&k_s[r * QS_STRIDE + d4 * 4] = v;
    }
    __syncthreads();

    // scores: thread -> 4 q-rows (qg) x 8 keys (kg + 16j)
    {
        const int qg = tid >> 4, kg = tid & 15;
        float acc[4][8];
#pragma unroll
        for (int i = 0; i < 4; i++)
#pragma unroll
            for (int j = 0; j < 8; j++) acc[i][j] = 0.f;

        const float4* q4 = (const float4*)q_s;
        const float4* k4 = (const float4*)k_s;
#pragma unroll 4
        for (int d4 = 0; d4 < 16; d4++) {
            float4 qv[4], kk[8];
#pragma unroll
            for (int i = 0; i < 4; i++) qv[i] = q4[(qg * 4 + i) * 17 + d4];
#pragma unroll
            for (int j = 0; j < 8; j++) kk[j] = k4[(kg + 16 * j) * 17 + d4];
#pragma unroll
            for (int i = 0; i < 4; i++)
#pragma unroll
                for (int j = 0; j < 8; j++)
                    acc[i][j] += qv[i].x * kk[j].x + qv[i].y * kk[j].y
                               + qv[i].z * kk[j].z + qv[i].w * kk[j].w;
        }
#pragma unroll
        for (int i = 0; i < 4; i++)
#pragma unroll
            for (int j = 0; j < 8; j++)
                sc[(qg * 4 + i) * SC_STRIDE + kg + 16 * j] = acc[i][j] * 0.125f;
    }
    __syncthreads();

    // overwrite k_s with v
#pragma unroll
    for (int j = 0; j < 8; j++) {
        const int f = tid + 256 * j;
        const int r = f >> 4, d4 = f & 15;
        float4 v = *(const float4*)(vb + (size_t)r * KV_DIM + d4 * 4);
        *(float4*)&k_s[r * QS_STRIDE + d4 * 4] = v;
    }

    // softmax: 4 threads per row
    {
        const int row = tid >> 2, part = tid & 3;
        float* srow = sc + row * SC_STRIDE + part;
        float mx = -FLT_MAX;
#pragma unroll
        for (int j = 0; j < 32; j++) mx = fmaxf(mx, srow[j * 4]);
        mx = fmaxf(mx, __shfl_xor_sync(0xffffffffu, mx, 1));
        mx = fmaxf(mx, __shfl_xor_sync(0xffffffffu, mx, 2));
        float s = 0.f;
#pragma unroll
        for (int j = 0; j < 32; j++) {
            float e = __expf(srow[j * 4] - mx);
            srow[j * 4] = e;
            s += e;
        }
        s += __shfl_xor_sync(0xffffffffu, s, 1);
        s += __shfl_xor_sync(0xffffffffu, s, 2);
        const float inv = 1.0f / s;
#pragma unroll
        for (int j = 0; j < 32; j++) srow[j * 4] *= inv;
    }
    __syncthreads();

    // PV: thread -> 4 q-rows (qg) x 4 d (dg float4); write fp16
    {
        const int qg = tid >> 4, dg = tid & 15;
        float4 acc[4];
#pragma unroll
        for (int i = 0; i < 4; i++) acc[i] = make_float4(0.f, 0.f, 0.f, 0.f);
        const float4* v4 = (const float4*)k_s;
#pragma unroll 4
        for (int k = 0; k < 128; k++) {
            float4 vv = v4[k * 17 + dg];
#pragma unroll
            for (int i = 0; i < 4; i++) {
                const float p = sc[(qg * 4 + i) * SC_STRIDE + k];
                acc[i].x += p * vv.x; acc[i].y += p * vv.y;
                acc[i].z += p * vv.z; acc[i].w += p * vv.w;
            }
        }
#pragma unroll
        for (int i = 0; i < 4; i++) {
            __half2 h0 = __floats2half2_rn(acc[i].x, acc[i].y);
            __half2 h1 = __floats2half2_rn(acc[i].z, acc[i].w);
            uint2 o;
            o.x = *(uint32_t*)&h0;
            o.y = *(uint32_t*)&h1;
            __half* dst = ao + ((size_t)bt * HW + qr0 + qg * 4 + i) * HIDDEN + h * D_HEAD + dg * 4;
            *(uint2*)dst = o;
        }
    }
}

// ---------------------------------------------------------------------------
// Launch
// ---------------------------------------------------------------------------
extern "C" void kernel_launch(void* const* d_in, const int* in_sizes, int n_in,
                              void* d_out, int out_size)
{
    const float* x       = (const float*)d_in[0];
    const float* latents = (const float*)d_in[1];
    const float* g1      = (const float*)d_in[2];
    const float* b1      = (const float*)d_in[3];
    const float* g2      = (const float*)d_in[4];
    const float* b2      = (const float*)d_in[5];
    const float* Wq      = (const float*)d_in[6];
    const float* Wkv     = (const float*)d_in[7];
    const float* Wo      = (const float*)d_in[8];
    float* out           = (float*)d_out;

    __half *xnh, *lnh, *aoh, *wqh, *wkvh, *woh;
    float *q, *kvb;
    cudaGetSymbolAddress((void**)&xnh,  g_xnh);
    cudaGetSymbolAddress((void**)&lnh,  g_lnh);
    cudaGetSymbolAddress((void**)&q,    g_q);
    cudaGetSymbolAddress((void**)&kvb,  g_kv);
    cudaGetSymbolAddress((void**)&aoh,  g_aoh);
    cudaGetSymbolAddress((void**)&wqh,  g_wqh);
    cudaGetSymbolAddress((void**)&wkvh, g_wkvh);
    cudaGetSymbolAddress((void**)&woh,  g_woh);

    cudaFuncSetAttribute(gemm_f16,    cudaFuncAttributeMaxDynamicSharedMemorySize, G2_SMEM);
    cudaFuncSetAttribute(attn_kernel, cudaFuncAttributeMaxDynamicSharedMemorySize, ATTN_SMEM);

    // weight transpose+convert to half [N][K]
    transpose_h<<<dim3(HIDDEN / 32, C_DIM / 32), dim3(32, 8)>>>(Wq,  wqh,  C_DIM, HIDDEN);
    transpose_h<<<dim3(KV_DIM / 32, C_DIM / 32), dim3(32, 8)>>>(Wkv, wkvh, C_DIM, KV_DIM);
    transpose_h<<<dim3(C_DIM / 32, HIDDEN / 32), dim3(32, 8)>>>(Wo,  woh,  HIDDEN, C_DIM);

    ln_kernel<<<ROWS_X, 256>>>(x, g1, b1, xnh);
    ln_kernel<<<ROWS_L, 256>>>(latents, g2, b2, lnh);

    gemm_f16<<<dim3(ROWS_L / BMT, HIDDEN / BNT), 256, G2_SMEM>>>(lnh, wqh,  q,   ROWS_L, HIDDEN, C_DIM);
    gemm_f16<<<dim3(ROWS_X / BMT, KV_DIM / BNT), 256, G2_SMEM>>>(xnh, wkvh, kvb, ROWS_X, KV_DIM, C_DIM);

    attn_kernel<<<dim3(HW / 64, N_HEADS, BT), 256, ATTN_SMEM>>>(q, kvb, aoh);

    gemm_f16<<<dim3(ROWS_L / BMT, C_DIM / BNT), 256, G2_SMEM>>>(aoh, woh, out, ROWS_L, C_DIM, HIDDEN);
}

// round 8
// speedup vs baseline: 1.8809x; 1.1129x over previous
#include <cuda_runtime.h>
#include <cuda_fp16.h>
#include <cstdint>
#include <cfloat>

// ---------------------------------------------------------------------------
// Problem dims (fixed)
// ---------------------------------------------------------------------------
#define C_DIM   3072
#define HIDDEN  3072
#define KV_DIM  6144
#define N_HEADS 48
#define D_HEAD  64
#define BT      4
#define AA      128
#define HW      1024
#define ROWS_X  (BT * AA)    // 512
#define ROWS_L  (BT * HW)    // 4096

// ---------------------------------------------------------------------------
// Scratch (device globals: allocation-free rule)
// ---------------------------------------------------------------------------
__device__ __half g_xnh[ROWS_X * C_DIM];
__device__ __half g_lnh[ROWS_L * C_DIM];
__device__ float  g_q  [ROWS_L * HIDDEN];
__device__ float  g_kv [ROWS_X * KV_DIM];
__device__ __half g_aoh[ROWS_L * HIDDEN];
__device__ __half g_wqh [HIDDEN * C_DIM];   // WqT  half [N=3072][K=3072]
__device__ __half g_wkvh[KV_DIM * C_DIM];   // WkvT half [N=6144][K=3072]
__device__ __half g_woh [C_DIM * HIDDEN];   // WoT  half [N=3072][K=3072]

// ---------------------------------------------------------------------------
// Helpers (sm_100-safe: mma.sync fp16 + ldmatrix + cp.async only)
// ---------------------------------------------------------------------------
__device__ __forceinline__ void mma_f16(float* c, const uint32_t* a, const uint32_t* b) {
    asm volatile(
        "mma.sync.aligned.m16n8k16.row.col.f32.f16.f16.f32 "
        "{%0,%1,%2,%3}, {%4,%5,%6,%7}, {%8,%9}, {%0,%1,%2,%3};\n"
        : "+f"(c[0]), "+f"(c[1]), "+f"(c[2]), "+f"(c[3])
        : "r"(a[0]), "r"(a[1]), "r"(a[2]), "r"(a[3]), "r"(b[0]), "r"(b[1]));
}

__device__ __forceinline__ void ldsm_x4(uint32_t* r, uint32_t addr) {
    asm volatile(
        "ldmatrix.sync.aligned.m8n8.x4.shared.b16 {%0,%1,%2,%3}, [%4];\n"
        : "=r"(r[0]), "=r"(r[1]), "=r"(r[2]), "=r"(r[3]) : "r"(addr));
}

__device__ __forceinline__ uint32_t smem_u32(const void* p) {
    uint32_t a;
    asm("{ .reg .u64 t; cvta.to.shared.u64 t, %1; cvt.u32.u64 %0, t; }" : "=r"(a) : "l"(p));
    return a;
}

__device__ __forceinline__ void cpa16(uint32_t dst, const void* src) {
    asm volatile("cp.async.cg.shared.global [%0], [%1], 16;\n" :: "r"(dst), "l"(src) : "memory");
}
#define CP_COMMIT() asm volatile("cp.async.commit_group;\n" ::: "memory")
#define CP_WAIT1()  asm volatile("cp.async.wait_group 1;\n" ::: "memory")

// ---------------------------------------------------------------------------
// LayerNorm: fp32 math, writes fp16 (only feeds fp16 tensor-core GEMMs)
// ---------------------------------------------------------------------------
__global__ __launch_bounds__(256)
void ln_kernel(const float* __restrict__ x, const float* __restrict__ gamma,
               const float* __restrict__ beta, __half* __restrict__ y)
{
    const int row = blockIdx.x;
    const int tid = threadIdx.x;
    const float* xr = x + (size_t)row * C_DIM;
    __half*      yr = y + (size_t)row * C_DIM;

    float4 v[3];
    float s = 0.f, s2 = 0.f;
#pragma unroll
    for (int j = 0; j < 3; j++) {
        v[j] = *(const float4*)(xr + (size_t)(tid + 256 * j) * 4);
        s  += v[j].x + v[j].y + v[j].z + v[j].w;
        s2 += v[j].x*v[j].x + v[j].y*v[j].y + v[j].z*v[j].z + v[j].w*v[j].w;
    }
#pragma unroll
    for (int o = 16; o > 0; o >>= 1) {
        s  += __shfl_xor_sync(0xffffffffu, s, o);
        s2 += __shfl_xor_sync(0xffffffffu, s2, o);
    }
    __shared__ float red[2][8];
    const int w = tid >> 5, lane = tid & 31;
    if (lane == 0) { red[0][w] = s; red[1][w] = s2; }
    __syncthreads();
    float ts = 0.f, ts2 = 0.f;
#pragma unroll
    for (int i = 0; i < 8; i++) { ts += red[0][i]; ts2 += red[1][i]; }
    const float mean = ts * (1.0f / C_DIM);
    const float var  = ts2 * (1.0f / C_DIM) - mean * mean;
    const float rstd = rsqrtf(var + 1e-5f);

#pragma unroll
    for (int j = 0; j < 3; j++) {
        const int c4 = (tid + 256 * j) * 4;
        float4 g = *(const float4*)(gamma + c4);
        float4 b = *(const float4*)(beta  + c4);
        __half2 h0 = __floats2half2_rn((v[j].x - mean) * rstd * g.x + b.x,
                                       (v[j].y - mean) * rstd * g.y + b.y);
        __half2 h1 = __floats2half2_rn((v[j].z - mean) * rstd * g.z + b.z,
                                       (v[j].w - mean) * rstd * g.w + b.w);
        uint2 o;
        o.x = *(uint32_t*)&h0;
        o.y = *(uint32_t*)&h1;
        *(uint2*)(yr + c4) = o;
    }
}

// ---------------------------------------------------------------------------
// Transpose+convert: W[K][N] fp32 -> WT[N][K] fp16
// ---------------------------------------------------------------------------
__global__ __launch_bounds__(256)
void transpose_h(const float* __restrict__ W, __half* __restrict__ WT, int K, int N)
{
    __shared__ float t[32][33];
    const int tx = threadIdx.x, ty = threadIdx.y;
    const int n = blockIdx.x * 32 + tx;
    const int k = blockIdx.y * 32 + ty;
#pragma unroll
    for (int j = 0; j < 32; j += 8)
        t[ty + j][tx] = W[(size_t)(k + j) * N + n];
    __syncthreads();
    const int n2 = blockIdx.x * 32 + ty;
    const int k2 = blockIdx.y * 32 + tx;
#pragma unroll
    for (int j = 0; j < 32; j += 8)
        WT[(size_t)(n2 + j) * K + k2] = __float2half_rn(t[tx][ty + j]);
}

// ---------------------------------------------------------------------------
// FP16 GEMM v3: C[M,N] fp32 = A[M,K] half (row-major) * Bt[N,K] half ^T
// 128x128 block, BK=32, 8 warps (2m x 4n, warp tile 64x32),
// mma.m16n8k16, ldmatrix fragment loads, 3-stage cp.async.
// M%128==0, N%128==0, K%32==0.
// ---------------------------------------------------------------------------
#define BMT 128
#define BNT 128
#define BKT 32
#define A_STRH 40                       // halves per smem row (32 + 8 pad)
#define STG_H  (128 * A_STRH)           // 5120 halves per tile (A or B)
#define STG_B  (STG_H * 2)              // 10240 bytes
#define G2_SMEM (3 * 2 * STG_B)         // 61440 B

__global__ __launch_bounds__(256, 2)
void gemm_f16(const __half* __restrict__ A, const __half* __restrict__ Bt,
              float* __restrict__ C, int M, int N, int K)
{
    extern __shared__ __half smh[];
    const uint32_t sbase = smem_u32(smh);

    const int tid  = threadIdx.x;
    const int lane = tid & 31;
    const int w    = tid >> 5;
    const int wm   = w >> 2;          // 0..1
    const int wn   = w & 3;           // 0..3
    const int g    = lane >> 2;       // 0..7
    const int tg   = lane & 3;        // 0..3
    const int m0   = blockIdx.x * BMT;
    const int n0   = blockIdx.y * BNT;

    const int nk = K / BKT;

    // ldmatrix lane address components (derived to match scalar-load frag layout)
    // A .x4: matrix m = {rows 0-7 | 8-15} x {k 0-7 | 8-15}
    const uint32_t a_row = (uint32_t)(wm * 64) + ((lane >> 3) & 1) * 8 + (lane & 7);
    const uint32_t a_col = (uint32_t)(lane >> 4) * 8;
    // B .x4 (pair p covers ni=2p,2p+1): m = {ni, k0 | ni, k8 | ni+1, k0 | ni+1, k8}
    const uint32_t b_row = (uint32_t)(wn * 32) + ((lane >> 4) & 1) * 8 + (lane & 7);
    const uint32_t b_col = ((lane >> 3) & 1) * 8;

    // staging: tile rows (128) x 4 chunks of 16B; thread does rows tid>>2, +64
    const int srow = tid >> 2, schk = tid & 3;

    auto fill = [&](int s, int kc) {
        const uint32_t aoff = sbase + (uint32_t)s * STG_B;
        const uint32_t boff = sbase + (uint32_t)(3 + s) * STG_B;
        cpa16(aoff + srow * (A_STRH * 2) + schk * 16,
              A + (size_t)(m0 + srow) * K + kc + schk * 8);
        cpa16(aoff + (srow + 64) * (A_STRH * 2) + schk * 16,
              A + (size_t)(m0 + srow + 64) * K + kc + schk * 8);
        cpa16(boff + srow * (A_STRH * 2) + schk * 16,
              Bt + (size_t)(n0 + srow) * K + kc + schk * 8);
        cpa16(boff + (srow + 64) * (A_STRH * 2) + schk * 16,
              Bt + (size_t)(n0 + srow + 64) * K + kc + schk * 8);
        CP_COMMIT();
    };

    float acc[4][4][4];
#pragma unroll
    for (int mi = 0; mi < 4; mi++)
#pragma unroll
        for (int ni = 0; ni < 4; ni++)
#pragma unroll
            for (int r = 0; r < 4; r++) acc[mi][ni][r] = 0.f;

    fill(0, 0);
    fill(1, BKT);

    for (int kt = 0; kt < nk; ++kt) {
        CP_WAIT1();
        __syncthreads();

        if (kt + 2 < nk) fill((kt + 2) % 3, (kt + 2) * BKT);
        else             CP_COMMIT();   // empty group keeps wait counts aligned

        const int s = kt % 3;
        const uint32_t aBase = sbase + (uint32_t)s * STG_B + (a_row * A_STRH + a_col) * 2;
        const uint32_t bBase = sbase + (uint32_t)(3 + s) * STG_B + (b_row * A_STRH + b_col) * 2;

#pragma unroll
        for (int k0 = 0; k0 < 32; k0 += 16) {
            uint32_t a[4][4], bf[8];
#pragma unroll
            for (int mi = 0; mi < 4; mi++)
                ldsm_x4(a[mi], aBase + (mi * 16 * A_STRH + k0) * 2);
            ldsm_x4(bf,     bBase + k0 * 2);                       // b[0],b[1]
            ldsm_x4(bf + 4, bBase + (16 * A_STRH + k0) * 2);       // b[2],b[3]
#pragma unroll
            for (int mi = 0; mi < 4; mi++)
#pragma unroll
                for (int ni = 0; ni < 4; ni++)
                    mma_f16(acc[mi][ni], a[mi], bf + ni * 2);
        }
    }

    // epilogue (c0,c1 @ (g, 2tg); c2,c3 @ (g+8, 2tg))
#pragma unroll
    for (int mi = 0; mi < 4; mi++) {
        const int r = m0 + wm * 64 + mi * 16 + g;
#pragma unroll
        for (int ni = 0; ni < 4; ni++) {
            const int c = n0 + wn * 32 + ni * 8 + 2 * tg;
            float2 lo = make_float2(acc[mi][ni][0], acc[mi][ni][1]);
            float2 hi = make_float2(acc[mi][ni][2], acc[mi][ni][3]);
            *(float2*)&C[(size_t)r * N + c]       = lo;
            *(float2*)&C[(size_t)(r + 8) * N + c] = hi;
        }
    }
}

// ---------------------------------------------------------------------------
// Attention (proven fp32 core; output fp16 for the Wo GEMM)
// ---------------------------------------------------------------------------
#define QS_STRIDE 68
#define SC_STRIDE 132
#define ATTN_SMEM ((64 * QS_STRIDE + 128 * QS_STRIDE + 64 * SC_STRIDE) * 4)

__global__ __launch_bounds__(256)
void attn_kernel(const float* __restrict__ q, const float* __restrict__ kv,
                 __half* __restrict__ ao)
{
    extern __shared__ float sm[];
    float* q_s = sm;                                    // 64 x 68
    float* k_s = sm + 64 * QS_STRIDE;                   // 128 x 68 (then v)
    float* sc  = sm + 64 * QS_STRIDE + 128 * QS_STRIDE; // 64 x 132

    const int tid = threadIdx.x;
    const int cq  = blockIdx.x;
    const int h   = blockIdx.y;
    const int bt  = blockIdx.z;
    const int qr0 = cq * 64;

    const float* qb = q  + ((size_t)bt * HW + qr0) * HIDDEN + h * D_HEAD;
    const float* kb = kv + (size_t)bt * AA * KV_DIM + h * D_HEAD;
    const float* vb = kb + HIDDEN;

#pragma unroll
    for (int j = 0; j < 4; j++) {
        const int f = tid + 256 * j;
        const int r = f >> 4, d4 = f & 15;
        float4 v = *(const float4*)(qb + (size_t)r * HIDDEN + d4 * 4);
        *(float4*)&q_s[r * QS_STRIDE + d4 * 4] = v;
    }
#pragma unroll
    for (int j = 0; j < 8; j++) {
        const int f = tid + 256 * j;
        const int r = f >> 4, d4 = f & 15;
        float4 v = *(const float4*)(kb + (size_t)r * KV_DIM + d4 * 4);
        *(float4*)&k_s[r * QS_STRIDE + d4 * 4] = v;
    }
    __syncthreads();

    // scores: thread -> 4 q-rows (qg) x 8 keys (kg + 16j)
    {
        const int qg = tid >> 4, kg = tid & 15;
        float acc[4][8];
#pragma unroll
        for (int i = 0; i < 4; i++)
#pragma unroll
            for (int j = 0; j < 8; j++) acc[i][j] = 0.f;

        const float4* q4 = (const float4*)q_s;
        const float4* k4 = (const float4*)k_s;
#pragma unroll 4
        for (int d4 = 0; d4 < 16; d4++) {
            float4 qv[4], kk[8];
#pragma unroll
            for (int i = 0; i < 4; i++) qv[i] = q4[(qg * 4 + i) * 17 + d4];
#pragma unroll
            for (int j = 0; j < 8; j++) kk[j] = k4[(kg + 16 * j) * 17 + d4];
#pragma unroll
            for (int i = 0; i < 4; i++)
#pragma unroll
                for (int j = 0; j < 8; j++)
                    acc[i][j] += qv[i].x * kk[j].x + qv[i].y * kk[j].y
                               + qv[i].z * kk[j].z + qv[i].w * kk[j].w;
        }
#pragma unroll
        for (int i = 0; i < 4; i++)
#pragma unroll
            for (int j = 0; j < 8; j++)
                sc[(qg * 4 + i) * SC_STRIDE + kg + 16 * j] = acc[i][j] * 0.125f;
    }
    __syncthreads();

    // overwrite k_s with v
#pragma unroll
    for (int j = 0; j < 8; j++) {
        const int f = tid + 256 * j;
        const int r = f >> 4, d4 = f & 15;
        float4 v = *(const float4*)(vb + (size_t)r * KV_DIM + d4 * 4);
        *(float4*)&k_s[r * QS_STRIDE + d4 * 4] = v;
    }

    // softmax: 4 threads per row
    {
        const int row = tid >> 2, part = tid & 3;
        float* srow = sc + row * SC_STRIDE + part;
        float mx = -FLT_MAX;
#pragma unroll
        for (int j = 0; j < 32; j++) mx = fmaxf(mx, srow[j * 4]);
        mx = fmaxf(mx, __shfl_xor_sync(0xffffffffu, mx, 1));
        mx = fmaxf(mx, __shfl_xor_sync(0xffffffffu, mx, 2));
        float s = 0.f;
#pragma unroll
        for (int j = 0; j < 32; j++) {
            float e = __expf(srow[j * 4] - mx);
            srow[j * 4] = e;
            s += e;
        }
        s += __shfl_xor_sync(0xffffffffu, s, 1);
        s += __shfl_xor_sync(0xffffffffu, s, 2);
        const float inv = 1.0f / s;
#pragma unroll
        for (int j = 0; j < 32; j++) srow[j * 4] *= inv;
    }
    __syncthreads();

    // PV: thread -> 4 q-rows (qg) x 4 d (dg float4); write fp16
    {
        const int qg = tid >> 4, dg = tid & 15;
        float4 acc[4];
#pragma unroll
        for (int i = 0; i < 4; i++) acc[i] = make_float4(0.f, 0.f, 0.f, 0.f);
        const float4* v4 = (const float4*)k_s;
#pragma unroll 4
        for (int k = 0; k < 128; k++) {
            float4 vv = v4[k * 17 + dg];
#pragma unroll
            for (int i = 0; i < 4; i++) {
                const float p = sc[(qg * 4 + i) * SC_STRIDE + k];
                acc[i].x += p * vv.x; acc[i].y += p * vv.y;
                acc[i].z += p * vv.z; acc[i].w += p * vv.w;
            }
        }
#pragma unroll
        for (int i = 0; i < 4; i++) {
            __half2 h0 = __floats2half2_rn(acc[i].x, acc[i].y);
            __half2 h1 = __floats2half2_rn(acc[i].z, acc[i].w);
            uint2 o;
            o.x = *(uint32_t*)&h0;
            o.y = *(uint32_t*)&h1;
            __half* dst = ao + ((size_t)bt * HW + qr0 + qg * 4 + i) * HIDDEN + h * D_HEAD + dg * 4;
            *(uint2*)dst = o;
        }
    }
}

// ---------------------------------------------------------------------------
// Launch
// ---------------------------------------------------------------------------
extern "C" void kernel_launch(void* const* d_in, const int* in_sizes, int n_in,
                              void* d_out, int out_size)
{
    const float* x       = (const float*)d_in[0];
    const float* latents = (const float*)d_in[1];
    const float* g1      = (const float*)d_in[2];
    const float* b1      = (const float*)d_in[3];
    const float* g2      = (const float*)d_in[4];
    const float* b2      = (const float*)d_in[5];
    const float* Wq      = (const float*)d_in[6];
    const float* Wkv     = (const float*)d_in[7];
    const float* Wo      = (const float*)d_in[8];
    float* out           = (float*)d_out;

    __half *xnh, *lnh, *aoh, *wqh, *wkvh, *woh;
    float *q, *kvb;
    cudaGetSymbolAddress((void**)&xnh,  g_xnh);
    cudaGetSymbolAddress((void**)&lnh,  g_lnh);
    cudaGetSymbolAddress((void**)&q,    g_q);
    cudaGetSymbolAddress((void**)&kvb,  g_kv);
    cudaGetSymbolAddress((void**)&aoh,  g_aoh);
    cudaGetSymbolAddress((void**)&wqh,  g_wqh);
    cudaGetSymbolAddress((void**)&wkvh, g_wkvh);
    cudaGetSymbolAddress((void**)&woh,  g_woh);

    cudaFuncSetAttribute(gemm_f16,    cudaFuncAttributeMaxDynamicSharedMemorySize, G2_SMEM);
    cudaFuncSetAttribute(attn_kernel, cudaFuncAttributeMaxDynamicSharedMemorySize, ATTN_SMEM);

    // weight transpose+convert to half [N][K]
    transpose_h<<<dim3(HIDDEN / 32, C_DIM / 32), dim3(32, 8)>>>(Wq,  wqh,  C_DIM, HIDDEN);
    transpose_h<<<dim3(KV_DIM / 32, C_DIM / 32), dim3(32, 8)>>>(Wkv, wkvh, C_DIM, KV_DIM);
    transpose_h<<<dim3(C_DIM / 32, HIDDEN / 32), dim3(32, 8)>>>(Wo,  woh,  HIDDEN, C_DIM);

    ln_kernel<<<ROWS_X, 256>>>(x, g1, b1, xnh);
    ln_kernel<<<ROWS_L, 256>>>(latents, g2, b2, lnh);

    gemm_f16<<<dim3(ROWS_L / BMT, HIDDEN / BNT), 256, G2_SMEM>>>(lnh, wqh,  q,   ROWS_L, HIDDEN, C_DIM);
    gemm_f16<<<dim3(ROWS_X / BMT, KV_DIM / BNT), 256, G2_SMEM>>>(xnh, wkvh, kvb, ROWS_X, KV_DIM, C_DIM);

    attn_kernel<<<dim3(HW / 64, N_HEADS, BT), 256, ATTN_SMEM>>>(q, kvb, aoh);

    gemm_f16<<<dim3(ROWS_L / BMT, C_DIM / BNT), 256, G2_SMEM>>>(aoh, woh, out, ROWS_L, C_DIM, HIDDEN);
}

// round 9
// speedup vs baseline: 2.2396x; 1.1907x over previous
#include <cuda_runtime.h>
#include <cuda_fp16.h>
#include <cstdint>
#include <cfloat>

// ---------------------------------------------------------------------------
// Problem dims (fixed)
// ---------------------------------------------------------------------------
#define C_DIM   3072
#define HIDDEN  3072
#define KV_DIM  6144
#define N_HEADS 48
#define D_HEAD  64
#define BT      4
#define AA      128
#define HW      1024
#define ROWS_X  (BT * AA)    // 512
#define ROWS_L  (BT * HW)    // 4096

// ---------------------------------------------------------------------------
// Scratch (device globals: allocation-free rule)
// ---------------------------------------------------------------------------
__device__ __half g_xnh[ROWS_X * C_DIM];
__device__ __half g_lnh[ROWS_L * C_DIM];
__device__ __half g_qh [ROWS_L * HIDDEN];
__device__ __half g_kvh[ROWS_X * KV_DIM];
__device__ __half g_aoh[ROWS_L * HIDDEN];
__device__ __half g_wqh [HIDDEN * C_DIM];   // WqT  half [N=3072][K=3072]
__device__ __half g_wkvh[KV_DIM * C_DIM];   // WkvT half [N=6144][K=3072]
__device__ __half g_woh [C_DIM * HIDDEN];   // WoT  half [N=3072][K=3072]

// ---------------------------------------------------------------------------
// Helpers (sm_100-safe: mma.sync fp16 + ldmatrix + cp.async only)
// ---------------------------------------------------------------------------
__device__ __forceinline__ void mma_f16(float* c, const uint32_t* a, const uint32_t* b) {
    asm volatile(
        "mma.sync.aligned.m16n8k16.row.col.f32.f16.f16.f32 "
        "{%0,%1,%2,%3}, {%4,%5,%6,%7}, {%8,%9}, {%0,%1,%2,%3};\n"
        : "+f"(c[0]), "+f"(c[1]), "+f"(c[2]), "+f"(c[3])
        : "r"(a[0]), "r"(a[1]), "r"(a[2]), "r"(a[3]), "r"(b[0]), "r"(b[1]));
}

__device__ __forceinline__ void ldsm_x4(uint32_t* r, uint32_t addr) {
    asm volatile(
        "ldmatrix.sync.aligned.m8n8.x4.shared.b16 {%0,%1,%2,%3}, [%4];\n"
        : "=r"(r[0]), "=r"(r[1]), "=r"(r[2]), "=r"(r[3]) : "r"(addr));
}

__device__ __forceinline__ uint32_t smem_u32(const void* p) {
    uint32_t a;
    asm("{ .reg .u64 t; cvta.to.shared.u64 t, %1; cvt.u32.u64 %0, t; }" : "=r"(a) : "l"(p));
    return a;
}

__device__ __forceinline__ void cpa16(uint32_t dst, const void* src) {
    asm volatile("cp.async.cg.shared.global [%0], [%1], 16;\n" :: "r"(dst), "l"(src) : "memory");
}
#define CP_COMMIT() asm volatile("cp.async.commit_group;\n" ::: "memory")
#define CP_WAIT1()  asm volatile("cp.async.wait_group 1;\n" ::: "memory")

__device__ __forceinline__ uint32_t pack_h2(float a, float b) {
    __half2 h = __floats2half2_rn(a, b);
    return *(uint32_t*)&h;
}

// ---------------------------------------------------------------------------
// LayerNorm: fp32 math, writes fp16
// ---------------------------------------------------------------------------
__global__ __launch_bounds__(256)
void ln_kernel(const float* __restrict__ x, const float* __restrict__ gamma,
               const float* __restrict__ beta, __half* __restrict__ y)
{
    const int row = blockIdx.x;
    const int tid = threadIdx.x;
    const float* xr = x + (size_t)row * C_DIM;
    __half*      yr = y + (size_t)row * C_DIM;

    float4 v[3];
    float s = 0.f, s2 = 0.f;
#pragma unroll
    for (int j = 0; j < 3; j++) {
        v[j] = *(const float4*)(xr + (size_t)(tid + 256 * j) * 4);
        s  += v[j].x + v[j].y + v[j].z + v[j].w;
        s2 += v[j].x*v[j].x + v[j].y*v[j].y + v[j].z*v[j].z + v[j].w*v[j].w;
    }
#pragma unroll
    for (int o = 16; o > 0; o >>= 1) {
        s  += __shfl_xor_sync(0xffffffffu, s, o);
        s2 += __shfl_xor_sync(0xffffffffu, s2, o);
    }
    __shared__ float red[2][8];
    const int w = tid >> 5, lane = tid & 31;
    if (lane == 0) { red[0][w] = s; red[1][w] = s2; }
    __syncthreads();
    float ts = 0.f, ts2 = 0.f;
#pragma unroll
    for (int i = 0; i < 8; i++) { ts += red[0][i]; ts2 += red[1][i]; }
    const float mean = ts * (1.0f / C_DIM);
    const float var  = ts2 * (1.0f / C_DIM) - mean * mean;
    const float rstd = rsqrtf(var + 1e-5f);

#pragma unroll
    for (int j = 0; j < 3; j++) {
        const int c4 = (tid + 256 * j) * 4;
        float4 g = *(const float4*)(gamma + c4);
        float4 b = *(const float4*)(beta  + c4);
        uint2 o;
        o.x = pack_h2((v[j].x - mean) * rstd * g.x + b.x,
                      (v[j].y - mean) * rstd * g.y + b.y);
        o.y = pack_h2((v[j].z - mean) * rstd * g.z + b.z,
                      (v[j].w - mean) * rstd * g.w + b.w);
        *(uint2*)(yr + c4) = o;
    }
}

// ---------------------------------------------------------------------------
// Transpose+convert: W[K][N] fp32 -> WT[N][K] fp16
// ---------------------------------------------------------------------------
__global__ __launch_bounds__(256)
void transpose_h(const float* __restrict__ W, __half* __restrict__ WT, int K, int N)
{
    __shared__ float t[32][33];
    const int tx = threadIdx.x, ty = threadIdx.y;
    const int n = blockIdx.x * 32 + tx;
    const int k = blockIdx.y * 32 + ty;
#pragma unroll
    for (int j = 0; j < 32; j += 8)
        t[ty + j][tx] = W[(size_t)(k + j) * N + n];
    __syncthreads();
    const int n2 = blockIdx.x * 32 + ty;
    const int k2 = blockIdx.y * 32 + tx;
#pragma unroll
    for (int j = 0; j < 32; j += 8)
        WT[(size_t)(n2 + j) * K + k2] = __float2half_rn(t[tx][ty + j]);
}

// ---------------------------------------------------------------------------
// FP16 GEMM: C[M,N] = A[M,K] half (row-major) * Bt[N,K] half ^T
// OutT = float or __half. 128x128 block, BK=32, mma.m16n8k16 + ldmatrix,
// 3-stage cp.async. M%128==0, N%128==0, K%32==0.
// ---------------------------------------------------------------------------
#define BMT 128
#define BNT 128
#define BKT 32
#define A_STRH 40
#define STG_H  (128 * A_STRH)
#define STG_B  (STG_H * 2)
#define G2_SMEM (3 * 2 * STG_B)         // 61440 B

template <typename OutT>
__global__ __launch_bounds__(256, 2)
void gemm_f16(const __half* __restrict__ A, const __half* __restrict__ Bt,
              OutT* __restrict__ C, int M, int N, int K)
{
    extern __shared__ __half smh[];
    const uint32_t sbase = smem_u32(smh);

    const int tid  = threadIdx.x;
    const int lane = tid & 31;
    const int w    = tid >> 5;
    const int wm   = w >> 2;
    const int wn   = w & 3;
    const int g    = lane >> 2;
    const int tg   = lane & 3;
    const int m0   = blockIdx.x * BMT;
    const int n0   = blockIdx.y * BNT;

    const int nk = K / BKT;

    const uint32_t a_row = (uint32_t)(wm * 64) + ((lane >> 3) & 1) * 8 + (lane & 7);
    const uint32_t a_col = (uint32_t)(lane >> 4) * 8;
    const uint32_t b_row = (uint32_t)(wn * 32) + ((lane >> 4) & 1) * 8 + (lane & 7);
    const uint32_t b_col = ((lane >> 3) & 1) * 8;

    const int srow = tid >> 2, schk = tid & 3;

    auto fill = [&](int s, int kc) {
        const uint32_t aoff = sbase + (uint32_t)s * STG_B;
        const uint32_t boff = sbase + (uint32_t)(3 + s) * STG_B;
        cpa16(aoff + srow * (A_STRH * 2) + schk * 16,
              A + (size_t)(m0 + srow) * K + kc + schk * 8);
        cpa16(aoff + (srow + 64) * (A_STRH * 2) + schk * 16,
              A + (size_t)(m0 + srow + 64) * K + kc + schk * 8);
        cpa16(boff + srow * (A_STRH * 2) + schk * 16,
              Bt + (size_t)(n0 + srow) * K + kc + schk * 8);
        cpa16(boff + (srow + 64) * (A_STRH * 2) + schk * 16,
              Bt + (size_t)(n0 + srow + 64) * K + kc + schk * 8);
        CP_COMMIT();
    };

    float acc[4][4][4];
#pragma unroll
    for (int mi = 0; mi < 4; mi++)
#pragma unroll
        for (int ni = 0; ni < 4; ni++)
#pragma unroll
            for (int r = 0; r < 4; r++) acc[mi][ni][r] = 0.f;

    fill(0, 0);
    fill(1, BKT);

    for (int kt = 0; kt < nk; ++kt) {
        CP_WAIT1();
        __syncthreads();

        if (kt + 2 < nk) fill((kt + 2) % 3, (kt + 2) * BKT);
        else             CP_COMMIT();

        const int s = kt % 3;
        const uint32_t aBase = sbase + (uint32_t)s * STG_B + (a_row * A_STRH + a_col) * 2;
        const uint32_t bBase = sbase + (uint32_t)(3 + s) * STG_B + (b_row * A_STRH + b_col) * 2;

#pragma unroll
        for (int k0 = 0; k0 < 32; k0 += 16) {
            uint32_t a[4][4], bf[8];
#pragma unroll
            for (int mi = 0; mi < 4; mi++)
                ldsm_x4(a[mi], aBase + (mi * 16 * A_STRH + k0) * 2);
            ldsm_x4(bf,     bBase + k0 * 2);
            ldsm_x4(bf + 4, bBase + (16 * A_STRH + k0) * 2);
#pragma unroll
            for (int mi = 0; mi < 4; mi++)
#pragma unroll
                for (int ni = 0; ni < 4; ni++)
                    mma_f16(acc[mi][ni], a[mi], bf + ni * 2);
        }
    }

#pragma unroll
    for (int mi = 0; mi < 4; mi++) {
        const int r = m0 + wm * 64 + mi * 16 + g;
#pragma unroll
        for (int ni = 0; ni < 4; ni++) {
            const int c = n0 + wn * 32 + ni * 8 + 2 * tg;
            if constexpr (sizeof(OutT) == 4) {
                *(float2*)&C[(size_t)r * N + c]       = make_float2(acc[mi][ni][0], acc[mi][ni][1]);
                *(float2*)&C[(size_t)(r + 8) * N + c] = make_float2(acc[mi][ni][2], acc[mi][ni][3]);
            } else {
                *(uint32_t*)&C[(size_t)r * N + c]       = pack_h2(acc[mi][ni][0], acc[mi][ni][1]);
                *(uint32_t*)&C[(size_t)(r + 8) * N + c] = pack_h2(acc[mi][ni][2], acc[mi][ni][3]);
            }
        }
    }
}

// ---------------------------------------------------------------------------
// Attention v2: tensor-core QK^T + PV, register softmax.
// CTA = (128 q-rows, head, bt), 8 warps; warp owns 16 q-rows.
// S-accumulator tiles double as PV A-fragments (layout identity).
// ---------------------------------------------------------------------------
#define AQ_STR 72     // halves per Q/K smem row (64 + 8 pad)
#define VT_STR 136    // halves per Vt row (128 + 8 pad)
#define ATTN2_SMEM ((2 * 128 * AQ_STR + 64 * VT_STR) * 2)   // 54272 B

__global__ __launch_bounds__(256)
void attn2_kernel(const __half* __restrict__ qh, const __half* __restrict__ kvh,
                  __half* __restrict__ ao)
{
    extern __shared__ __half sm2[];
    const uint32_t sq = smem_u32(sm2);
    const uint32_t sk = sq + 128 * AQ_STR * 2;
    const uint32_t sv = sk + 128 * AQ_STR * 2;
    __half* Vt = sm2 + 2 * 128 * AQ_STR;

    const int tid  = threadIdx.x;
    const int lane = tid & 31;
    const int w    = tid >> 5;
    const int g    = lane >> 2;
    const int tg   = lane & 3;
    const int cq   = blockIdx.x;
    const int h    = blockIdx.y;
    const int bt   = blockIdx.z;
    const int qr0  = cq * 128;

    const __half* qb = qh  + ((size_t)bt * HW + qr0) * HIDDEN + h * D_HEAD;
    const __half* kb = kvh + (size_t)bt * AA * KV_DIM + h * D_HEAD;
    const __half* vb = kb + HIDDEN;

    // stage Q (128x64) and K (128x64), 16B chunks
#pragma unroll
    for (int j = 0; j < 4; j++) {
        const int f = tid + 256 * j;             // 0..1023
        const int r = f >> 3, c8 = (f & 7) * 8;
        *(uint4*)(sm2 + r * AQ_STR + c8) = *(const uint4*)(qb + (size_t)r * HIDDEN + c8);
        *(uint4*)(sm2 + 128 * AQ_STR + r * AQ_STR + c8) = *(const uint4*)(kb + (size_t)r * KV_DIM + c8);
    }
    // stage V transposed: Vt[d][key]
#pragma unroll
    for (int j = 0; j < 4; j++) {
        const int f = tid + 256 * j;
        const int r = f >> 3, c8 = (f & 7) * 8;  // key r, d chunk c8
        uint4 vv = *(const uint4*)(vb + (size_t)r * KV_DIM + c8);
        const __half* hs = (const __half*)&vv;
#pragma unroll
        for (int t = 0; t < 8; t++)
            Vt[(c8 + t) * VT_STR + r] = hs[t];
    }
    __syncthreads();

    // ldmatrix lane addresses
    const uint32_t aAddr = sq + (((uint32_t)(w * 16) + (lane & 15)) * AQ_STR + (lane >> 4) * 8) * 2;
    const uint32_t kAddr = sk + ((((lane >> 4) & 1) * 8 + (lane & 7)) * AQ_STR + ((lane >> 3) & 1) * 8) * 2;
    const uint32_t vAddr = sv + ((((lane >> 4) & 1) * 8 + (lane & 7)) * VT_STR + ((lane >> 3) & 1) * 8) * 2;

    // S = Q K^T : warp rows w*16..+15, 16 n8-tiles over 128 keys, K-dim 64
    float sacc[16][4];
#pragma unroll
    for (int j = 0; j < 16; j++)
#pragma unroll
        for (int r = 0; r < 4; r++) sacc[j][r] = 0.f;

#pragma unroll
    for (int ks = 0; ks < 4; ks++) {
        const int k0 = ks * 16;
        uint32_t a[4];
        ldsm_x4(a, aAddr + k0 * 2);
#pragma unroll
        for (int p = 0; p < 8; p++) {
            uint32_t bf[4];
            ldsm_x4(bf, kAddr + (p * 16 * AQ_STR + k0) * 2);
            mma_f16(sacc[2 * p],     a, bf);
            mma_f16(sacc[2 * p + 1], a, bf + 2);
        }
    }

    // softmax over 128 cols; thread owns rows g (vals [0],[1]) and g+8 ([2],[3])
    {
        float mx0 = -FLT_MAX, mx1 = -FLT_MAX;
#pragma unroll
        for (int j = 0; j < 16; j++) {
            sacc[j][0] *= 0.125f; sacc[j][1] *= 0.125f;
            sacc[j][2] *= 0.125f; sacc[j][3] *= 0.125f;
            mx0 = fmaxf(mx0, fmaxf(sacc[j][0], sacc[j][1]));
            mx1 = fmaxf(mx1, fmaxf(sacc[j][2], sacc[j][3]));
        }
        mx0 = fmaxf(mx0, __shfl_xor_sync(0xffffffffu, mx0, 1));
        mx0 = fmaxf(mx0, __shfl_xor_sync(0xffffffffu, mx0, 2));
        mx1 = fmaxf(mx1, __shfl_xor_sync(0xffffffffu, mx1, 1));
        mx1 = fmaxf(mx1, __shfl_xor_sync(0xffffffffu, mx1, 2));
        float s0 = 0.f, s1 = 0.f;
#pragma unroll
        for (int j = 0; j < 16; j++) {
            sacc[j][0] = __expf(sacc[j][0] - mx0); s0 += sacc[j][0];
            sacc[j][1] = __expf(sacc[j][1] - mx0); s0 += sacc[j][1];
            sacc[j][2] = __expf(sacc[j][2] - mx1); s1 += sacc[j][2];
            sacc[j][3] = __expf(sacc[j][3] - mx1); s1 += sacc[j][3];
        }
        s0 += __shfl_xor_sync(0xffffffffu, s0, 1);
        s0 += __shfl_xor_sync(0xffffffffu, s0, 2);
        s1 += __shfl_xor_sync(0xffffffffu, s1, 1);
        s1 += __shfl_xor_sync(0xffffffffu, s1, 2);
        const float i0 = 1.0f / s0, i1 = 1.0f / s1;
#pragma unroll
        for (int j = 0; j < 16; j++) {
            sacc[j][0] *= i0; sacc[j][1] *= i0;
            sacc[j][2] *= i1; sacc[j][3] *= i1;
        }
    }

    // O = P V : 8 n8-tiles over 64 d, K-dim 128 (8 k-steps).
    // A-frag for k-step t comes straight from sacc[2t], sacc[2t+1].
    float oacc[8][4];
#pragma unroll
    for (int j = 0; j < 8; j++)
#pragma unroll
        for (int r = 0; r < 4; r++) oacc[j][r] = 0.f;

#pragma unroll
    for (int t = 0; t < 8; t++) {
        uint32_t pa[4];
        pa[0] = pack_h2(sacc[2 * t][0],     sacc[2 * t][1]);
        pa[1] = pack_h2(sacc[2 * t][2],     sacc[2 * t][3]);
        pa[2] = pack_h2(sacc[2 * t + 1][0], sacc[2 * t + 1][1]);
        pa[3] = pack_h2(sacc[2 * t + 1][2], sacc[2 * t + 1][3]);
#pragma unroll
        for (int p = 0; p < 4; p++) {
            uint32_t bf[4];
            ldsm_x4(bf, vAddr + (p * 16 * VT_STR + t * 16) * 2);
            mma_f16(oacc[2 * p],     pa, bf);
            mma_f16(oacc[2 * p + 1], pa, bf + 2);
        }
    }

    // write O rows (qr0 + w*16 + g, +8), cols h*64 + 8j + 2tg, as half2
    {
        __half* orow0 = ao + ((size_t)bt * HW + qr0 + w * 16 + g) * HIDDEN + h * D_HEAD + 2 * tg;
        __half* orow1 = orow0 + 8 * (size_t)HIDDEN;
#pragma unroll
        for (int j = 0; j < 8; j++) {
            *(uint32_t*)(orow0 + 8 * j) = pack_h2(oacc[j][0], oacc[j][1]);
            *(uint32_t*)(orow1 + 8 * j) = pack_h2(oacc[j][2], oacc[j][3]);
        }
    }
}

// ---------------------------------------------------------------------------
// Launch
// ---------------------------------------------------------------------------
extern "C" void kernel_launch(void* const* d_in, const int* in_sizes, int n_in,
                              void* d_out, int out_size)
{
    const float* x       = (const float*)d_in[0];
    const float* latents = (const float*)d_in[1];
    const float* g1      = (const float*)d_in[2];
    const float* b1      = (const float*)d_in[3];
    const float* g2      = (const float*)d_in[4];
    const float* b2      = (const float*)d_in[5];
    const float* Wq      = (const float*)d_in[6];
    const float* Wkv     = (const float*)d_in[7];
    const float* Wo      = (const float*)d_in[8];
    float* out           = (float*)d_out;

    __half *xnh, *lnh, *qh, *kvh, *aoh, *wqh, *wkvh, *woh;
    cudaGetSymbolAddress((void**)&xnh,  g_xnh);
    cudaGetSymbolAddress((void**)&lnh,  g_lnh);
    cudaGetSymbolAddress((void**)&qh,   g_qh);
    cudaGetSymbolAddress((void**)&kvh,  g_kvh);
    cudaGetSymbolAddress((void**)&aoh,  g_aoh);
    cudaGetSymbolAddress((void**)&wqh,  g_wqh);
    cudaGetSymbolAddress((void**)&wkvh, g_wkvh);
    cudaGetSymbolAddress((void**)&woh,  g_woh);

    cudaFuncSetAttribute(gemm_f16<float>,  cudaFuncAttributeMaxDynamicSharedMemorySize, G2_SMEM);
    cudaFuncSetAttribute(gemm_f16<__half>, cudaFuncAttributeMaxDynamicSharedMemorySize, G2_SMEM);
    cudaFuncSetAttribute(attn2_kernel,     cudaFuncAttributeMaxDynamicSharedMemorySize, ATTN2_SMEM);

    transpose_h<<<dim3(HIDDEN / 32, C_DIM / 32), dim3(32, 8)>>>(Wq,  wqh,  C_DIM, HIDDEN);
    transpose_h<<<dim3(KV_DIM / 32, C_DIM / 32), dim3(32, 8)>>>(Wkv, wkvh, C_DIM, KV_DIM);
    transpose_h<<<dim3(C_DIM / 32, HIDDEN / 32), dim3(32, 8)>>>(Wo,  woh,  HIDDEN, C_DIM);

    ln_kernel<<<ROWS_X, 256>>>(x, g1, b1, xnh);
    ln_kernel<<<ROWS_L, 256>>>(latents, g2, b2, lnh);

    gemm_f16<__half><<<dim3(ROWS_L / BMT, HIDDEN / BNT), 256, G2_SMEM>>>(lnh, wqh,  qh,  ROWS_L, HIDDEN, C_DIM);
    gemm_f16<__half><<<dim3(ROWS_X / BMT, KV_DIM / BNT), 256, G2_SMEM>>>(xnh, wkvh, kvh, ROWS_X, KV_DIM, C_DIM);

    attn2_kernel<<<dim3(HW / 128, N_HEADS, BT), 256, ATTN2_SMEM>>>(qh, kvh, aoh);

    gemm_f16<float><<<dim3(ROWS_L / BMT, C_DIM / BNT), 256, G2_SMEM>>>(aoh, woh, out, ROWS_L, C_DIM, HIDDEN);
}